// round 14
// baseline (speedup 1.0000x reference)
#include <cuda_runtime.h>
#include <cuda_fp16.h>
#include <math.h>
#include <stdint.h>

#define Bsz 64
#define Lsz 2048
#define BL (Bsz*Lsz)      // 131072
#define EMBD 128
#define DM 128
#define DI 256
#define DS 16
#define DR 8
#define NL 4
#define NCH 32            // scan chunks
#define CLEN 64           // chunk length

// ---------------- scratch (static device arrays; no cudaMalloc) ------------
__device__ __half g_xn16[BL*DM];         // embed output fp16 (front conv input)
__device__ float  g_x [BL*DM];           // residual stream (fp32)
__device__ float  g_rf[BL];              // rmsnorm scale factor per row
__device__ __half g_xr16[BL*DM];         // fp16(g_x * rf)  (in_proj input)
__device__ __half g_xz16[(size_t)BL*512];// in_proj out fp16: [..:256]=xi, [256:]=z
__device__ __half g_xc16[(size_t)BL*DI]; // depthwise conv + silu = u (fp16)
__device__ float  g_dbl[(size_t)BL*40];  // x_proj out (dtlow|B|C) fp32
__device__ __half g_y16[(size_t)BL*DI];  // gated scan out (fp16)
__device__ float  g_hc[(size_t)Bsz*NCH*DI*DS]; // chunk states
__device__ float  g_sd[(size_t)Bsz*NCH*DI];    // chunk sum(dt)
__device__ __half g_wext16[DM*384];      // repacked front conv weight fp16
__device__ __half g_inw16[NL*512*DM];    // in_proj weights fp16 (norm_w folded)
__device__ __half g_xpw16[NL*40*DI];     // x_proj weights fp16
__device__ __half g_outw16[NL*DM*DI];    // out_proj weights fp16
__device__ float  g_pool[Bsz*DM];
__device__ float  g_h1[Bsz*512];
__device__ float  g_h2[Bsz*512];

// =================== helpers ===============================================
__device__ __forceinline__ uint32_t s2u(const void* p) {
    uint32_t a;
    asm("{ .reg .u64 t; cvta.to.shared.u64 t, %1; cvt.u32.u64 %0, t; }" : "=r"(a) : "l"(p));
    return a;
}
__device__ __forceinline__ uint32_t swz(uint32_t off) {   // SW128 swizzle
    return off ^ ((off >> 3) & 0x70);
}
__device__ __forceinline__ void ldm_x4(uint32_t* r, uint32_t addr) {
    asm volatile("ldmatrix.sync.aligned.m8n8.x4.shared.b16 {%0,%1,%2,%3}, [%4];"
        : "=r"(r[0]), "=r"(r[1]), "=r"(r[2]), "=r"(r[3]) : "r"(addr));
}
__device__ __forceinline__ void mma_f16(float* d, const uint32_t* a, const uint32_t* b) {
    asm volatile(
        "mma.sync.aligned.m16n8k16.row.col.f32.f16.f16.f32 "
        "{%0,%1,%2,%3}, {%4,%5,%6,%7}, {%8,%9}, {%0,%1,%2,%3};"
        : "+f"(d[0]), "+f"(d[1]), "+f"(d[2]), "+f"(d[3])
        : "r"(a[0]), "r"(a[1]), "r"(a[2]), "r"(a[3]), "r"(b[0]), "r"(b[1]));
}
__device__ __forceinline__ void cpa16(uint32_t dst, const void* src, int sz) {
    asm volatile("cp.async.cg.shared.global [%0], [%1], 16, %2;"
        :: "r"(dst), "l"(src), "r"(sz));
}
#define CPA_COMMIT() asm volatile("cp.async.commit_group;" ::: "memory")
#define CPA_WAIT1()  asm volatile("cp.async.wait_group 1;" ::: "memory")

// ============== cp.async pipelined fp16 GEMM via mma.sync ===================
// block tile 128x128, K-chunk 64, 3-stage cp.async pipeline.
// AMODE: 0 = plain fp16 A; 2 = front conv (A16=g_xn16, shifted rows)
// CHALF: store C fp16; WRF: rmsnorm factor of output rows -> g_rf
template<int AMODE, bool CHALF, bool WRF>
__global__ void __launch_bounds__(256, 2)
k_hmm(const __half* __restrict__ A16, const __half* __restrict__ W16,
      const float* __restrict__ bias, const float* __restrict__ res,
      float* __restrict__ C, __half* __restrict__ C16,
      int K, int ldC, int Nreal, int Nstore, int relu)
{
    constexpr int STG = 32768;     // A 16K | B 16K per stage, 3 stages
    extern __shared__ char smem[];
    __shared__ float rsum[128];
    uint32_t sbase = s2u(smem);

    int tid = threadIdx.x;
    int wid = tid >> 5, lane = tid & 31;
    int mw = wid & 3, nw = wid >> 2;          // 4 x 2 warp grid
    long bm = (long)blockIdx.x * 128;
    int bn = blockIdx.y * 128;

    int lmat = lane >> 3, lrow = lane & 7;
    int a_row = mw * 32 + (lmat & 1) * 8 + lrow;
    int a_koff = (lmat >> 1) * 16;
    int b_row = nw * 64 + (lmat >> 1) * 8 + lrow;
    int b_koff = (lmat & 1) * 16;

    bool wact = (bn + nw * 64) < Nreal;
    int KB = K / 64;

    float acc[2][8][4];
    #pragma unroll
    for (int f = 0; f < 2; f++)
        #pragma unroll
        for (int n = 0; n < 8; n++)
            #pragma unroll
            for (int j = 0; j < 4; j++) acc[f][n][j] = 0.f;

    auto ISSUE = [&](int st) {
        if (st >= KB) return;
        uint32_t abuf = sbase + (st % 3) * STG;
        uint32_t bbuf = abuf + 16384;
        #pragma unroll
        for (int j = 0; j < 4; j++) {
            int c = j * 256 + tid;
            int r = c >> 3, ch = c & 7;
            uint32_t dst = abuf + swz((uint32_t)(r * 128 + ch * 16));
            const __half* src;
            int sz = 16;
            if constexpr (AMODE == 0) {
                src = A16 + (size_t)(bm + r) * K + st * 64 + ch * 8;
            } else {
                int tap = st >> 1;
                int e = (st & 1) * 64 + ch * 8;
                long m = bm + r;
                int l = (int)(m & (Lsz - 1));
                int lsrc = l + tap - 1;
                src = A16 + (size_t)(m + tap - 1) * 128 + e;
                if (lsrc < 0 || lsrc >= Lsz) sz = 0;
            }
            cpa16(dst, src, sz);
        }
        #pragma unroll
        for (int j = 0; j < 4; j++) {
            int c = j * 256 + tid;
            int n = c >> 3, ch = c & 7;
            uint32_t dst = bbuf + swz((uint32_t)(n * 128 + ch * 16));
            const __half* src = W16 + (size_t)(bn + n) * K + st * 64 + ch * 8;
            int sz = (bn + n < Nreal) ? 16 : 0;
            cpa16(dst, src, sz);
        }
    };

    ISSUE(0); CPA_COMMIT();
    ISSUE(1); CPA_COMMIT();

    for (int kb = 0; kb < KB; kb++) {
        CPA_WAIT1();
        __syncthreads();
        if (wact) {
            uint32_t abuf = sbase + (kb % 3) * STG;
            uint32_t bbuf = abuf + 16384;
            #pragma unroll
            for (int kk = 0; kk < 4; kk++) {
                uint32_t ah[2][4];
                #pragma unroll
                for (int f = 0; f < 2; f++) {
                    uint32_t sw = swz((uint32_t)((a_row + f * 16) * 128 + kk * 32 + a_koff));
                    ldm_x4(ah[f], abuf + sw);
                }
                #pragma unroll
                for (int np = 0; np < 4; np++) {
                    uint32_t bh[4];
                    uint32_t sw = swz((uint32_t)((b_row + np * 16) * 128 + kk * 32 + b_koff));
                    ldm_x4(bh, bbuf + sw);
                    #pragma unroll
                    for (int f = 0; f < 2; f++) {
                        mma_f16(acc[f][2*np+0], ah[f], bh + 0);
                        mma_f16(acc[f][2*np+1], ah[f], bh + 2);
                    }
                }
            }
        }
        ISSUE(kb + 2);
        CPA_COMMIT();
    }

    if constexpr (WRF) {
        if (tid < 128) rsum[tid] = 0.f;
        __syncthreads();
    }

    int g = lane >> 2, t2 = (lane & 3) * 2;
    #pragma unroll
    for (int f = 0; f < 2; f++) {
        float s0 = 0.f, s1 = 0.f;
        long r0 = bm + mw * 32 + f * 16 + g;
        long r1 = r0 + 8;
        #pragma unroll
        for (int nt = 0; nt < 8; nt++) {
            int col = bn + nw * 64 + nt * 8 + t2;
            if (col >= Nstore) continue;
            float2 d0 = make_float2(acc[f][nt][0], acc[f][nt][1]);
            float2 d1 = make_float2(acc[f][nt][2], acc[f][nt][3]);
            if (bias) { float b0 = bias[col], b1 = bias[col+1];
                        d0.x += b0; d0.y += b1; d1.x += b0; d1.y += b1; }
            if (res) {
                float2 q0 = *(const float2*)(res + (size_t)r0 * ldC + col);
                float2 q1 = *(const float2*)(res + (size_t)r1 * ldC + col);
                d0.x += q0.x; d0.y += q0.y; d1.x += q1.x; d1.y += q1.y;
            }
            if (relu) {
                d0.x = fmaxf(d0.x, 0.f); d0.y = fmaxf(d0.y, 0.f);
                d1.x = fmaxf(d1.x, 0.f); d1.y = fmaxf(d1.y, 0.f);
            }
            if constexpr (WRF) {
                s0 += d0.x * d0.x + d0.y * d0.y;
                s1 += d1.x * d1.x + d1.y * d1.y;
            }
            if constexpr (CHALF) {
                *(__half2*)(C16 + (size_t)r0 * ldC + col) = __floats2half2_rn(d0.x, d0.y);
                *(__half2*)(C16 + (size_t)r1 * ldC + col) = __floats2half2_rn(d1.x, d1.y);
            } else {
                *(float2*)(C + (size_t)r0 * ldC + col) = d0;
                *(float2*)(C + (size_t)r1 * ldC + col) = d1;
            }
        }
        if constexpr (WRF) {
            s0 += __shfl_xor_sync(0xffffffffu, s0, 1);
            s0 += __shfl_xor_sync(0xffffffffu, s0, 2);
            s1 += __shfl_xor_sync(0xffffffffu, s1, 1);
            s1 += __shfl_xor_sync(0xffffffffu, s1, 2);
            if ((lane & 3) == 0) {
                atomicAdd(&rsum[(int)(r0 - bm)], s0);
                atomicAdd(&rsum[(int)(r1 - bm)], s1);
            }
        }
    }
    if constexpr (WRF) {
        __syncthreads();
        if (tid < 128)
            g_rf[bm + tid] = rsqrtf(rsum[tid] * (1.f / DM) + 1e-5f);
    }
}

// ---------------- embed + batchnorm-ish scale -> fp16 ----------------------
__global__ void k_embed(const int* __restrict__ tok, const float* __restrict__ emb,
                        const float* __restrict__ bnw, const float* __restrict__ bnb)
{
    int idx = blockIdx.x * 256 + threadIdx.x;
    if (idx >= BL * EMBD) return;
    int e = idx & 127;
    int t = idx >> 7;
    float s = bnw[e] * rsqrtf(1.0f + 1e-5f);
    g_xn16[idx] = __float2half_rn(emb[tok[t] * EMBD + e] * s + bnb[e]);
}

__global__ void k_repack(const float* __restrict__ cw)
{
    int idx = blockIdx.x * 256 + threadIdx.x;
    if (idx >= DM * 384) return;
    int o = idx / 384, kg = idx % 384;
    int tap = kg >> 7, e = kg & 127;
    g_wext16[idx] = __float2half_rn(cw[(o * EMBD + e) * 3 + tap]);
}

__global__ void k_cvt(const float* __restrict__ src, __half* __restrict__ dst, int n)
{
    int i = blockIdx.x * 256 + threadIdx.x;
    if (i < n) dst[i] = __float2half_rn(src[i]);
}

// in_proj weights with norm_w folded (per layer)
__global__ void k_cvtw(const float* __restrict__ w, const float* __restrict__ nw,
                       __half* __restrict__ dst)
{
    int i = blockIdx.x * 256 + threadIdx.x;
    if (i >= NL * 512 * DM) return;
    int k = i & 127;
    int layer = i / (512 * DM);
    dst[i] = __float2half_rn(w[i] * nw[layer * DM + k]);
}

// g_xr16 = fp16(g_x * rf)
__global__ void k_normcopy()
{
    long idx4 = (long)blockIdx.x * 256 + threadIdx.x;   // BL*128/4 float4s
    float4 v = ((const float4*)g_x)[idx4];
    float rf = g_rf[idx4 >> 5];
    __half2* o = (__half2*)g_xr16 + idx4 * 2;
    o[0] = __floats2half2_rn(v.x * rf, v.y * rf);
    o[1] = __floats2half2_rn(v.z * rf, v.w * rf);
}

// ---------------- generic fp32 GEMM (small head layers) --------------------
__global__ void k_gemm(const float* __restrict__ A, const float* __restrict__ W,
                       const float* __restrict__ bias, const float* __restrict__ res,
                       float* __restrict__ C, int N, int K, int act)
{
    __shared__ float As[16][64];
    __shared__ float Ws[16][64];
    int tid = threadIdx.x;
    int tx = tid & 15, ty = tid >> 4;
    long bm = (long)blockIdx.x * 64;
    int bn = blockIdx.y * 64;
    int lrow = tid >> 2, lcol = (tid & 3) * 4;
    const float* Ap = A + (bm + lrow) * (size_t)K + lcol;
    int nrow = bn + lrow;
    const float* Wp = (nrow < N) ? (W + (size_t)nrow * K + lcol) : (const float*)0;
    float acc[4][4] = {};
    for (int kc = 0; kc < K; kc += 16) {
        float4 av = *(const float4*)(Ap + kc);
        float4 wv = make_float4(0.f, 0.f, 0.f, 0.f);
        if (Wp) wv = *(const float4*)(Wp + kc);
        As[lcol+0][lrow]=av.x; As[lcol+1][lrow]=av.y; As[lcol+2][lrow]=av.z; As[lcol+3][lrow]=av.w;
        Ws[lcol+0][lrow]=wv.x; Ws[lcol+1][lrow]=wv.y; Ws[lcol+2][lrow]=wv.z; Ws[lcol+3][lrow]=wv.w;
        __syncthreads();
        #pragma unroll
        for (int kk = 0; kk < 16; kk++) {
            float4 a4 = *(const float4*)&As[kk][ty*4];
            float4 w4 = *(const float4*)&Ws[kk][tx*4];
            acc[0][0]+=a4.x*w4.x; acc[0][1]+=a4.x*w4.y; acc[0][2]+=a4.x*w4.z; acc[0][3]+=a4.x*w4.w;
            acc[1][0]+=a4.y*w4.x; acc[1][1]+=a4.y*w4.y; acc[1][2]+=a4.y*w4.z; acc[1][3]+=a4.y*w4.w;
            acc[2][0]+=a4.z*w4.x; acc[2][1]+=a4.z*w4.y; acc[2][2]+=a4.z*w4.z; acc[2][3]+=a4.z*w4.w;
            acc[3][0]+=a4.w*w4.x; acc[3][1]+=a4.w*w4.y; acc[3][2]+=a4.w*w4.z; acc[3][3]+=a4.w*w4.w;
        }
        __syncthreads();
    }
    #pragma unroll
    for (int i = 0; i < 4; i++) {
        long row = bm + ty * 4 + i;
        #pragma unroll
        for (int j = 0; j < 4; j++) {
            int col = bn + tx * 4 + j;
            if (col < N) {
                float v = acc[i][j];
                if (bias) v += bias[col];
                if (res)  v += res[row * (size_t)N + col];
                if (act)  v = fmaxf(v, 0.f);
                C[row * (size_t)N + col] = v;
            }
        }
    }
}

// ---------------- depthwise causal conv (k=4) + silu, fp16 in/out ----------
__global__ void k_dwconv(const float* __restrict__ w, const float* __restrict__ bias)
{
    int b  = blockIdx.y;
    int l0 = blockIdx.x * 16;
    int d  = threadIdx.x;
    float w0 = w[d*4+0], w1 = w[d*4+1], w2 = w[d*4+2], w3 = w[d*4+3];
    float bb = bias[d];
    const __half* xp = g_xz16 + (size_t)b * Lsz * 512 + d;
    float v[19];
    #pragma unroll
    for (int j = 0; j < 19; j++) {
        int ls = l0 + j - 3;
        v[j] = (ls >= 0) ? __half2float(xp[(size_t)ls * 512]) : 0.f;
    }
    __half* op = g_xc16 + ((size_t)b * Lsz + l0) * DI + d;
    #pragma unroll
    for (int t = 0; t < 16; t++) {
        float a = v[t]*w0 + v[t+1]*w1 + v[t+2]*w2 + v[t+3]*w3 + bb;
        op[(size_t)t * DI] = __float2half_rn(a / (1.f + __expf(-a)));
    }
}

// ================= chunked selective scan (3-pass) ==========================
__device__ __forceinline__ void dt_smem(const float* __restrict__ row,
                                        float4 w0, float4 w1, float bd,
                                        float& dt, float& p)
{
    float4 r0 = *(const float4*)(row);
    float4 r1 = *(const float4*)(row + 4);
    float aa = bd + r0.x*w0.x + r0.y*w0.y + r0.z*w0.z + r0.w*w0.w
                  + r1.x*w1.x + r1.y*w1.y + r1.z*w1.z + r1.w*w1.w;
    float e = __expf(aa);
    p  = __fdividef(1.f, 1.f + e);
    dt = (aa > 15.f) ? aa : -__logf(p);
}

__global__ void __launch_bounds__(256)
k_scanA(const float* __restrict__ Alog,
        const float* __restrict__ dtw, const float* __restrict__ dtb)
{
    __shared__ float sdbl[CLEN * 40];
    int c = blockIdx.x, b = blockIdx.y, d = threadIdx.x;

    const float* gsrc = g_dbl + ((size_t)b * Lsz + c * CLEN) * 40;
    for (int i = d; i < CLEN * 40 / 4; i += 256)
        ((float4*)sdbl)[i] = ((const float4*)gsrc)[i];

    float4 w0 = ((const float4*)(dtw + d * 8))[0];
    float4 w1 = ((const float4*)(dtw + d * 8))[1];
    float bd = dtb[d];

    bool fast = true;
    float a[DS];
    #pragma unroll
    for (int s = 0; s < DS; s++) {
        a[s] = -expf(Alog[d * DS + s]);
        if (fabsf(a[s] + (float)(s + 1)) > 1e-4f * (float)(s + 1)) fast = false;
    }
    float h[DS];
    #pragma unroll
    for (int s = 0; s < DS; s++) h[s] = 0.f;
    float sumdt = 0.f;

    const __half* up = g_xc16 + ((size_t)b * Lsz + c * CLEN) * DI + d;
    __syncthreads();

    if (fast) {
        for (int l = 0; l < CLEN; l++) {
            const float* row = sdbl + l * 40;
            float dt, p;
            dt_smem(row, w0, w1, bd, dt, p);
            float w = dt * __half2float(up[(size_t)l * DI]);
            sumdt += dt;
            const float4* B4 = (const float4*)(row + 8);
            float p2 = p * p;
            float q1 = p, q2 = p2, q3 = p2 * p, q4 = p2 * p2;
            float base = 1.f;
            #pragma unroll
            for (int g = 0; g < 4; g++) {
                float4 Bv = B4[g];
                h[4*g+0] = (base*q1)*h[4*g+0] + w*Bv.x;
                h[4*g+1] = (base*q2)*h[4*g+1] + w*Bv.y;
                h[4*g+2] = (base*q3)*h[4*g+2] + w*Bv.z;
                h[4*g+3] = (base*q4)*h[4*g+3] + w*Bv.w;
                base = base * q4;
            }
        }
    } else {
        for (int l = 0; l < CLEN; l++) {
            const float* row = sdbl + l * 40;
            float dt, p;
            dt_smem(row, w0, w1, bd, dt, p);
            float w = dt * __half2float(up[(size_t)l * DI]);
            sumdt += dt;
            #pragma unroll
            for (int s = 0; s < DS; s++) {
                float dA = __expf(dt * a[s]);
                h[s] = dA * h[s] + w * row[8 + s];
            }
        }
    }
    float* slot = g_hc + (((size_t)b * NCH + c) * DI + d) * DS;
    #pragma unroll
    for (int q = 0; q < 4; q++)
        ((float4*)slot)[q] = make_float4(h[4*q], h[4*q+1], h[4*q+2], h[4*q+3]);
    g_sd[((size_t)b * NCH + c) * DI + d] = sumdt;
}

__global__ void __launch_bounds__(256)
k_scanB(const float* __restrict__ Alog)
{
    int b = blockIdx.x, d = threadIdx.x;
    float a[DS];
    #pragma unroll
    for (int s = 0; s < DS; s++) a[s] = -expf(Alog[d * DS + s]);
    float hp[DS];
    #pragma unroll
    for (int s = 0; s < DS; s++) hp[s] = 0.f;

    for (int c = 0; c < NCH; c++) {
        float* slot = g_hc + (((size_t)b * NCH + c) * DI + d) * DS;
        float sd = g_sd[((size_t)b * NCH + c) * DI + d];
        float hl[DS];
        #pragma unroll
        for (int q = 0; q < 4; q++) {
            float4 v = ((const float4*)slot)[q];
            hl[4*q] = v.x; hl[4*q+1] = v.y; hl[4*q+2] = v.z; hl[4*q+3] = v.w;
        }
        #pragma unroll
        for (int q = 0; q < 4; q++)
            ((float4*)slot)[q] = make_float4(hp[4*q], hp[4*q+1], hp[4*q+2], hp[4*q+3]);
        #pragma unroll
        for (int s = 0; s < DS; s++)
            hp[s] = __expf(a[s] * sd) * hp[s] + hl[s];
    }
}

__global__ void __launch_bounds__(256)
k_scanC(const float* __restrict__ Alog,
        const float* __restrict__ dtw, const float* __restrict__ dtb,
        const float* __restrict__ Dp)
{
    __shared__ float sdbl[CLEN * 40];
    int c = blockIdx.x, b = blockIdx.y, d = threadIdx.x;

    const float* gsrc = g_dbl + ((size_t)b * Lsz + c * CLEN) * 40;
    for (int i = d; i < CLEN * 40 / 4; i += 256)
        ((float4*)sdbl)[i] = ((const float4*)gsrc)[i];

    float4 w0 = ((const float4*)(dtw + d * 8))[0];
    float4 w1 = ((const float4*)(dtw + d * 8))[1];
    float bd = dtb[d];
    float Dv = Dp[d];

    bool fast = true;
    float a[DS];
    #pragma unroll
    for (int s = 0; s < DS; s++) {
        a[s] = -expf(Alog[d * DS + s]);
        if (fabsf(a[s] + (float)(s + 1)) > 1e-4f * (float)(s + 1)) fast = false;
    }
    float h[DS];
    const float* slot = g_hc + (((size_t)b * NCH + c) * DI + d) * DS;
    #pragma unroll
    for (int q = 0; q < 4; q++) {
        float4 v = ((const float4*)slot)[q];
        h[4*q] = v.x; h[4*q+1] = v.y; h[4*q+2] = v.z; h[4*q+3] = v.w;
    }

    const __half* up = g_xc16 + ((size_t)b * Lsz + c * CLEN) * DI + d;
    const __half* zp = g_xz16 + ((size_t)b * Lsz + c * CLEN) * 512 + 256 + d;
    __half*       yp = g_y16  + ((size_t)b * Lsz + c * CLEN) * DI + d;
    __syncthreads();

    if (fast) {
        for (int l = 0; l < CLEN; l++) {
            const float* row = sdbl + l * 40;
            float dt, p;
            dt_smem(row, w0, w1, bd, dt, p);
            float u = __half2float(up[(size_t)l * DI]);
            float z = __half2float(zp[(size_t)l * 512]);
            float w = dt * u;
            const float4* B4 = (const float4*)(row + 8);
            const float4* C4 = (const float4*)(row + 24);
            float p2 = p * p;
            float q1 = p, q2 = p2, q3 = p2 * p, q4 = p2 * p2;
            float y0 = 0.f, y1 = 0.f, y2 = 0.f, y3 = 0.f;
            float base = 1.f;
            #pragma unroll
            for (int g = 0; g < 4; g++) {
                float4 Bv = B4[g], Cv = C4[g];
                h[4*g+0] = (base*q1)*h[4*g+0] + w*Bv.x;
                h[4*g+1] = (base*q2)*h[4*g+1] + w*Bv.y;
                h[4*g+2] = (base*q3)*h[4*g+2] + w*Bv.z;
                h[4*g+3] = (base*q4)*h[4*g+3] + w*Bv.w;
                y0 += h[4*g+0]*Cv.x;
                y1 += h[4*g+1]*Cv.y;
                y2 += h[4*g+2]*Cv.z;
                y3 += h[4*g+3]*Cv.w;
                base = base * q4;
            }
            float y = (y0 + y1) + (y2 + y3);
            float sz = __fdividef(z, 1.f + __expf(-z));
            yp[(size_t)l * DI] = __float2half_rn((y + u * Dv) * sz);
        }
    } else {
        for (int l = 0; l < CLEN; l++) {
            const float* row = sdbl + l * 40;
            float dt, p;
            dt_smem(row, w0, w1, bd, dt, p);
            float u = __half2float(up[(size_t)l * DI]);
            float z = __half2float(zp[(size_t)l * 512]);
            float w = dt * u;
            float yacc = 0.f;
            #pragma unroll
            for (int s = 0; s < DS; s++) {
                float dA = __expf(dt * a[s]);
                h[s] = dA * h[s] + w * row[8 + s];
                yacc += h[s] * row[24 + s];
            }
            float sz = __fdividef(z, 1.f + __expf(-z));
            yp[(size_t)l * DI] = __float2half_rn((yacc + u * Dv) * sz);
        }
    }
}

// ---------------- masked mean pool: single kernel, block per batch ----------
__global__ void __launch_bounds__(256)
k_pool(const float* __restrict__ mask)
{
    __shared__ float part[256];
    __shared__ float mpart[2];
    int b = blockIdx.x;
    int e = threadIdx.x & 127;
    int hf = threadIdx.x >> 7;          // 0 or 1: halves of L
    const float* xp = g_x + ((size_t)b * Lsz + hf * (Lsz/2)) * DM + e;
    const float* mp = mask + (size_t)b * Lsz + hf * (Lsz/2);
    float acc = 0.f, ms = 0.f;
    for (int l = 0; l < Lsz/2; l++) {
        float m = mp[l];
        acc += xp[(size_t)l * DM] * m;
        ms += m;
    }
    part[threadIdx.x] = acc;
    if (e == 0) mpart[hf] = ms * 128.f;   // will divide by 128 later consistently
    __syncthreads();
    if (hf == 0) {
        float tot = part[e] + part[128 + e];
        float msum = (mpart[0] + mpart[1]) * (1.f / 128.f);
        g_pool[b * DM + e] = tot / fmaxf(msum, 1e-9f);
    }
}

__global__ void k_mlp3(const float* __restrict__ w, const float* __restrict__ bias,
                       float* __restrict__ out)
{
    int t = threadIdx.x;
    if (t >= Bsz * 3) return;
    int bb = t / 3, n = t - bb * 3;
    const float* hp = g_h2 + bb * 512;
    const float* wp = w + n * 512;
    float acc = bias[n];
    for (int k = 0; k < 512; k++) acc += hp[k] * wp[k];
    out[bb * 3 + n] = acc;
}

// ---------------- launch ----------------------------------------------------
extern "C" void kernel_launch(void* const* d_in, const int* in_sizes, int n_in,
                              void* d_out, int out_size)
{
    const int*   tokens = (const int*)  d_in[0];
    const float* mask   = (const float*)d_in[1];
    const float* emb    = (const float*)d_in[2];
    const float* bn_w   = (const float*)d_in[3];
    const float* bn_b   = (const float*)d_in[4];
    const float* conv_w = (const float*)d_in[5];
    const float* conv_b = (const float*)d_in[6];
    const float* in_w   = (const float*)d_in[7];
    const float* c1_w   = (const float*)d_in[8];
    const float* c1_b   = (const float*)d_in[9];
    const float* xp_w   = (const float*)d_in[10];
    const float* dtp_w  = (const float*)d_in[11];
    const float* dtp_b  = (const float*)d_in[12];
    const float* A_log  = (const float*)d_in[13];
    const float* D_p    = (const float*)d_in[14];
    const float* out_w  = (const float*)d_in[15];
    const float* norm_w = (const float*)d_in[16];
    const float* l1w    = (const float*)d_in[17];
    const float* l1b    = (const float*)d_in[18];
    const float* l2w    = (const float*)d_in[19];
    const float* l2b    = (const float*)d_in[20];
    const float* l3w    = (const float*)d_in[21];
    const float* l3b    = (const float*)d_in[22];
    float* out = (float*)d_out;

    float *p_x, *p_dbl, *p_pool, *p_h1, *p_h2;
    __half *p_xn16, *p_xr16, *p_xz16, *p_xc16, *p_y16, *p_wext16, *p_inw16, *p_xpw16, *p_outw16;
    cudaGetSymbolAddress((void**)&p_xn16,  g_xn16);
    cudaGetSymbolAddress((void**)&p_x,     g_x);
    cudaGetSymbolAddress((void**)&p_xr16,  g_xr16);
    cudaGetSymbolAddress((void**)&p_xz16,  g_xz16);
    cudaGetSymbolAddress((void**)&p_xc16,  g_xc16);
    cudaGetSymbolAddress((void**)&p_dbl,   g_dbl);
    cudaGetSymbolAddress((void**)&p_y16,   g_y16);
    cudaGetSymbolAddress((void**)&p_pool,  g_pool);
    cudaGetSymbolAddress((void**)&p_h1,    g_h1);
    cudaGetSymbolAddress((void**)&p_h2,    g_h2);
    cudaGetSymbolAddress((void**)&p_wext16,g_wext16);
    cudaGetSymbolAddress((void**)&p_inw16, g_inw16);
    cudaGetSymbolAddress((void**)&p_xpw16, g_xpw16);
    cudaGetSymbolAddress((void**)&p_outw16,g_outw16);

    const int SMB = 98304;  // 3 x (A 16K | B 16K)
    cudaFuncSetAttribute(k_hmm<0,false,false>, cudaFuncAttributeMaxDynamicSharedMemorySize, SMB);
    cudaFuncSetAttribute(k_hmm<0,false,true>,  cudaFuncAttributeMaxDynamicSharedMemorySize, SMB);
    cudaFuncSetAttribute(k_hmm<0,true,false>,  cudaFuncAttributeMaxDynamicSharedMemorySize, SMB);
    cudaFuncSetAttribute(k_hmm<2,false,true>,  cudaFuncAttributeMaxDynamicSharedMemorySize, SMB);

    // weight conversions (tiny)
    k_cvtw<<<(NL*512*DM + 255)/256, 256>>>(in_w, norm_w, p_inw16);
    k_cvt<<<(NL*40*DI  + 255)/256, 256>>>(xp_w,  p_xpw16,  NL*40*DI);
    k_cvt<<<(NL*DM*DI  + 255)/256, 256>>>(out_w, p_outw16, NL*DM*DI);
    k_repack<<<(DM * 384 + 255) / 256, 256>>>(conv_w);
    k_embed<<<BL * EMBD / 256, 256>>>(tokens, emb, bn_w, bn_b);

    // front conv: implicit GEMM, bias+relu -> g_x; also computes g_rf
    k_hmm<2,false,true><<<dim3(BL / 128, 1), 256, SMB>>>(
        p_xn16, p_wext16, conv_b, (const float*)0,
        p_x, (__half*)0, 384, 128, 128, 128, 1);

    for (int i = 0; i < NL; i++) {
        const float* Al = A_log + (size_t)i * DI * DS;
        const float* dw = dtp_w + (size_t)i * DI * DR;
        const float* db = dtp_b + (size_t)i * DI;

        // normalized fp16 copy of residual (rf from previous GEMM)
        k_normcopy<<<BL / 8, 256>>>();
        // in_proj (norm_w folded into weights) -> g_xz16
        k_hmm<0,true,false><<<dim3(BL / 128, 4), 256, SMB>>>(
            p_xr16, p_inw16 + (size_t)i * 512 * DM, (const float*)0, (const float*)0,
            (float*)0, p_xz16, 128, 512, 512, 512, 0);
        k_dwconv<<<dim3(Lsz / 16, Bsz), 256>>>(c1_w + (size_t)i * DI * 4, c1_b + (size_t)i * DI);
        // x_proj -> g_dbl
        k_hmm<0,false,false><<<dim3(BL / 128, 1), 256, SMB>>>(
            p_xc16, p_xpw16 + (size_t)i * 40 * DI, (const float*)0, (const float*)0,
            p_dbl, (__half*)0, 256, 40, 40, 40, 0);
        k_scanA<<<dim3(NCH, Bsz), 256>>>(Al, dw, db);
        k_scanB<<<Bsz, 256>>>(Al);
        k_scanC<<<dim3(NCH, Bsz), 256>>>(Al, dw, db, D_p + (size_t)i * DI);
        // out_proj: += residual -> g_x; also computes g_rf
        k_hmm<0,false,true><<<dim3(BL / 128, 1), 256, SMB>>>(
            p_y16, p_outw16 + (size_t)i * DM * DI, (const float*)0, p_x,
            p_x, (__half*)0, 256, 128, 128, 128, 0);
    }

    k_pool<<<Bsz, 256>>>(mask);
    k_gemm<<<dim3(1, 512 / 64), 256>>>(p_pool, l1w, l1b, (const float*)0, p_h1, 512, DM, 1);
    k_gemm<<<dim3(1, 512 / 64), 256>>>(p_h1,   l2w, l2b, (const float*)0, p_h2, 512, 512, 1);
    k_mlp3<<<1, 256>>>(l3w, l3b, out);
}

// round 15
// speedup vs baseline: 1.0135x; 1.0135x over previous
#include <cuda_runtime.h>
#include <cuda_fp16.h>
#include <math.h>
#include <stdint.h>

#define Bsz 64
#define Lsz 2048
#define BL (Bsz*Lsz)      // 131072
#define EMBD 128
#define DM 128
#define DI 256
#define DS 16
#define DR 8
#define NL 4
#define NCH 32            // scan chunks
#define CLEN 64           // chunk length

// ---------------- scratch (static device arrays; no cudaMalloc) ------------
__device__ __half g_xn16[BL*DM];         // embed output fp16 (front conv input)
__device__ float  g_x [BL*DM];           // residual stream (fp32)
__device__ float  g_rf[BL];              // rmsnorm scale factor per row
__device__ __half g_xr16[BL*DM];         // fp16(g_x * rf)  (in_proj input)
__device__ __half g_xz16[(size_t)BL*512];// in_proj out fp16: [..:256]=xi, [256:]=z
__device__ __half g_xc16[(size_t)BL*DI]; // depthwise conv + silu = u (fp16)
__device__ float  g_dbl[(size_t)BL*40];  // x_proj out (dtlow|B|C) fp32
__device__ __half g_y16[(size_t)BL*DI];  // gated scan out (fp16)
__device__ float  g_hc[(size_t)Bsz*NCH*DI*DS]; // chunk states
__device__ float  g_sd[(size_t)Bsz*NCH*DI];    // chunk sum(dt)
__device__ __half g_wext16[DM*384];      // repacked front conv weight fp16
__device__ __half g_inw16[NL*512*DM];    // in_proj weights fp16 (norm_w folded)
__device__ __half g_xpw16[NL*40*DI];     // x_proj weights fp16
__device__ __half g_outw16[NL*DM*DI];    // out_proj weights fp16
__device__ float  g_pool[Bsz*DM];
__device__ float  g_poolp[Bsz*16*DM];
__device__ float  g_msum[Bsz*16];
__device__ float  g_h1[Bsz*512];
__device__ float  g_h2[Bsz*512];

// =================== helpers ===============================================
__device__ __forceinline__ uint32_t s2u(const void* p) {
    uint32_t a;
    asm("{ .reg .u64 t; cvta.to.shared.u64 t, %1; cvt.u32.u64 %0, t; }" : "=r"(a) : "l"(p));
    return a;
}
__device__ __forceinline__ uint32_t swz(uint32_t off) {   // SW128 swizzle
    return off ^ ((off >> 3) & 0x70);
}
__device__ __forceinline__ void ldm_x4(uint32_t* r, uint32_t addr) {
    asm volatile("ldmatrix.sync.aligned.m8n8.x4.shared.b16 {%0,%1,%2,%3}, [%4];"
        : "=r"(r[0]), "=r"(r[1]), "=r"(r[2]), "=r"(r[3]) : "r"(addr));
}
__device__ __forceinline__ void mma_f16(float* d, const uint32_t* a, const uint32_t* b) {
    asm volatile(
        "mma.sync.aligned.m16n8k16.row.col.f32.f16.f16.f32 "
        "{%0,%1,%2,%3}, {%4,%5,%6,%7}, {%8,%9}, {%0,%1,%2,%3};"
        : "+f"(d[0]), "+f"(d[1]), "+f"(d[2]), "+f"(d[3])
        : "r"(a[0]), "r"(a[1]), "r"(a[2]), "r"(a[3]), "r"(b[0]), "r"(b[1]));
}
__device__ __forceinline__ void cpa16(uint32_t dst, const void* src, int sz) {
    asm volatile("cp.async.cg.shared.global [%0], [%1], 16, %2;"
        :: "r"(dst), "l"(src), "r"(sz));
}
#define CPA_COMMIT() asm volatile("cp.async.commit_group;" ::: "memory")
#define CPA_WAIT1()  asm volatile("cp.async.wait_group 1;" ::: "memory")

// ============== cp.async pipelined fp16 GEMM via mma.sync ===================
// block tile 128x128, K-chunk 64, 3-stage cp.async pipeline.
// AMODE: 0 = plain fp16 A; 2 = front conv (A16=g_xn16, shifted rows)
// CHALF: store C fp16; WRF: rmsnorm factor of output rows -> g_rf
template<int AMODE, bool CHALF, bool WRF>
__global__ void __launch_bounds__(256, 2)
k_hmm(const __half* __restrict__ A16, const __half* __restrict__ W16,
      const float* __restrict__ bias, const float* __restrict__ res,
      float* __restrict__ C, __half* __restrict__ C16,
      int K, int ldC, int Nreal, int Nstore, int relu)
{
    constexpr int STG = 32768;     // A 16K | B 16K per stage, 3 stages
    extern __shared__ char smem[];
    __shared__ float rsum[128];
    uint32_t sbase = s2u(smem);

    int tid = threadIdx.x;
    int wid = tid >> 5, lane = tid & 31;
    int mw = wid & 3, nw = wid >> 2;          // 4 x 2 warp grid
    long bm = (long)blockIdx.x * 128;
    int bn = blockIdx.y * 128;

    int lmat = lane >> 3, lrow = lane & 7;
    int a_row = mw * 32 + (lmat & 1) * 8 + lrow;
    int a_koff = (lmat >> 1) * 16;
    int b_row = nw * 64 + (lmat >> 1) * 8 + lrow;
    int b_koff = (lmat & 1) * 16;

    bool wact = (bn + nw * 64) < Nreal;
    int KB = K / 64;

    float acc[2][8][4];
    #pragma unroll
    for (int f = 0; f < 2; f++)
        #pragma unroll
        for (int n = 0; n < 8; n++)
            #pragma unroll
            for (int j = 0; j < 4; j++) acc[f][n][j] = 0.f;

    auto ISSUE = [&](int st) {
        if (st >= KB) return;
        uint32_t abuf = sbase + (st % 3) * STG;
        uint32_t bbuf = abuf + 16384;
        #pragma unroll
        for (int j = 0; j < 4; j++) {
            int c = j * 256 + tid;
            int r = c >> 3, ch = c & 7;
            uint32_t dst = abuf + swz((uint32_t)(r * 128 + ch * 16));
            const __half* src;
            int sz = 16;
            if constexpr (AMODE == 0) {
                src = A16 + (size_t)(bm + r) * K + st * 64 + ch * 8;
            } else {
                int tap = st >> 1;
                int e = (st & 1) * 64 + ch * 8;
                long m = bm + r;
                int l = (int)(m & (Lsz - 1));
                int lsrc = l + tap - 1;
                src = A16 + (size_t)(m + tap - 1) * 128 + e;
                if (lsrc < 0 || lsrc >= Lsz) sz = 0;
            }
            cpa16(dst, src, sz);
        }
        #pragma unroll
        for (int j = 0; j < 4; j++) {
            int c = j * 256 + tid;
            int n = c >> 3, ch = c & 7;
            uint32_t dst = bbuf + swz((uint32_t)(n * 128 + ch * 16));
            const __half* src = W16 + (size_t)(bn + n) * K + st * 64 + ch * 8;
            int sz = (bn + n < Nreal) ? 16 : 0;
            cpa16(dst, src, sz);
        }
    };

    ISSUE(0); CPA_COMMIT();
    ISSUE(1); CPA_COMMIT();

    for (int kb = 0; kb < KB; kb++) {
        CPA_WAIT1();
        __syncthreads();
        if (wact) {
            uint32_t abuf = sbase + (kb % 3) * STG;
            uint32_t bbuf = abuf + 16384;
            #pragma unroll
            for (int kk = 0; kk < 4; kk++) {
                uint32_t ah[2][4];
                #pragma unroll
                for (int f = 0; f < 2; f++) {
                    uint32_t sw = swz((uint32_t)((a_row + f * 16) * 128 + kk * 32 + a_koff));
                    ldm_x4(ah[f], abuf + sw);
                }
                #pragma unroll
                for (int np = 0; np < 4; np++) {
                    uint32_t bh[4];
                    uint32_t sw = swz((uint32_t)((b_row + np * 16) * 128 + kk * 32 + b_koff));
                    ldm_x4(bh, bbuf + sw);
                    #pragma unroll
                    for (int f = 0; f < 2; f++) {
                        mma_f16(acc[f][2*np+0], ah[f], bh + 0);
                        mma_f16(acc[f][2*np+1], ah[f], bh + 2);
                    }
                }
            }
        }
        ISSUE(kb + 2);
        CPA_COMMIT();
    }

    if constexpr (WRF) {
        if (tid < 128) rsum[tid] = 0.f;
        __syncthreads();
    }

    int g = lane >> 2, t2 = (lane & 3) * 2;
    #pragma unroll
    for (int f = 0; f < 2; f++) {
        float s0 = 0.f, s1 = 0.f;
        long r0 = bm + mw * 32 + f * 16 + g;
        long r1 = r0 + 8;
        #pragma unroll
        for (int nt = 0; nt < 8; nt++) {
            int col = bn + nw * 64 + nt * 8 + t2;
            if (col >= Nstore) continue;
            float2 d0 = make_float2(acc[f][nt][0], acc[f][nt][1]);
            float2 d1 = make_float2(acc[f][nt][2], acc[f][nt][3]);
            if (bias) { float b0 = bias[col], b1 = bias[col+1];
                        d0.x += b0; d0.y += b1; d1.x += b0; d1.y += b1; }
            if (res) {
                float2 q0 = *(const float2*)(res + (size_t)r0 * ldC + col);
                float2 q1 = *(const float2*)(res + (size_t)r1 * ldC + col);
                d0.x += q0.x; d0.y += q0.y; d1.x += q1.x; d1.y += q1.y;
            }
            if (relu) {
                d0.x = fmaxf(d0.x, 0.f); d0.y = fmaxf(d0.y, 0.f);
                d1.x = fmaxf(d1.x, 0.f); d1.y = fmaxf(d1.y, 0.f);
            }
            if constexpr (WRF) {
                s0 += d0.x * d0.x + d0.y * d0.y;
                s1 += d1.x * d1.x + d1.y * d1.y;
            }
            if constexpr (CHALF) {
                *(__half2*)(C16 + (size_t)r0 * ldC + col) = __floats2half2_rn(d0.x, d0.y);
                *(__half2*)(C16 + (size_t)r1 * ldC + col) = __floats2half2_rn(d1.x, d1.y);
            } else {
                *(float2*)(C + (size_t)r0 * ldC + col) = d0;
                *(float2*)(C + (size_t)r1 * ldC + col) = d1;
            }
        }
        if constexpr (WRF) {
            s0 += __shfl_xor_sync(0xffffffffu, s0, 1);
            s0 += __shfl_xor_sync(0xffffffffu, s0, 2);
            s1 += __shfl_xor_sync(0xffffffffu, s1, 1);
            s1 += __shfl_xor_sync(0xffffffffu, s1, 2);
            if ((lane & 3) == 0) {
                atomicAdd(&rsum[(int)(r0 - bm)], s0);
                atomicAdd(&rsum[(int)(r1 - bm)], s1);
            }
        }
    }
    if constexpr (WRF) {
        __syncthreads();
        if (tid < 128)
            g_rf[bm + tid] = rsqrtf(rsum[tid] * (1.f / DM) + 1e-5f);
    }
}

// ---------------- embed + batchnorm-ish scale -> fp16 ----------------------
__global__ void k_embed(const int* __restrict__ tok, const float* __restrict__ emb,
                        const float* __restrict__ bnw, const float* __restrict__ bnb)
{
    int idx = blockIdx.x * 256 + threadIdx.x;
    if (idx >= BL * EMBD) return;
    int e = idx & 127;
    int t = idx >> 7;
    float s = bnw[e] * rsqrtf(1.0f + 1e-5f);
    g_xn16[idx] = __float2half_rn(emb[tok[t] * EMBD + e] * s + bnb[e]);
}

__global__ void k_repack(const float* __restrict__ cw)
{
    int idx = blockIdx.x * 256 + threadIdx.x;
    if (idx >= DM * 384) return;
    int o = idx / 384, kg = idx % 384;
    int tap = kg >> 7, e = kg & 127;
    g_wext16[idx] = __float2half_rn(cw[(o * EMBD + e) * 3 + tap]);
}

__global__ void k_cvt(const float* __restrict__ src, __half* __restrict__ dst, int n)
{
    int i = blockIdx.x * 256 + threadIdx.x;
    if (i < n) dst[i] = __float2half_rn(src[i]);
}

// in_proj weights with norm_w folded (per layer)
__global__ void k_cvtw(const float* __restrict__ w, const float* __restrict__ nw,
                       __half* __restrict__ dst)
{
    int i = blockIdx.x * 256 + threadIdx.x;
    if (i >= NL * 512 * DM) return;
    int k = i & 127;
    int layer = i / (512 * DM);
    dst[i] = __float2half_rn(w[i] * nw[layer * DM + k]);
}

// g_xr16 = fp16(g_x * rf)
__global__ void k_normcopy()
{
    long idx4 = (long)blockIdx.x * 256 + threadIdx.x;   // BL*128/4 float4s
    float4 v = ((const float4*)g_x)[idx4];
    float rf = g_rf[idx4 >> 5];
    __half2* o = (__half2*)g_xr16 + idx4 * 2;
    o[0] = __floats2half2_rn(v.x * rf, v.y * rf);
    o[1] = __floats2half2_rn(v.z * rf, v.w * rf);
}

// ---------------- generic fp32 GEMM (small head layers) --------------------
__global__ void k_gemm(const float* __restrict__ A, const float* __restrict__ W,
                       const float* __restrict__ bias, const float* __restrict__ res,
                       float* __restrict__ C, int N, int K, int act)
{
    __shared__ float As[16][64];
    __shared__ float Ws[16][64];
    int tid = threadIdx.x;
    int tx = tid & 15, ty = tid >> 4;
    long bm = (long)blockIdx.x * 64;
    int bn = blockIdx.y * 64;
    int lrow = tid >> 2, lcol = (tid & 3) * 4;
    const float* Ap = A + (bm + lrow) * (size_t)K + lcol;
    int nrow = bn + lrow;
    const float* Wp = (nrow < N) ? (W + (size_t)nrow * K + lcol) : (const float*)0;
    float acc[4][4] = {};
    for (int kc = 0; kc < K; kc += 16) {
        float4 av = *(const float4*)(Ap + kc);
        float4 wv = make_float4(0.f, 0.f, 0.f, 0.f);
        if (Wp) wv = *(const float4*)(Wp + kc);
        As[lcol+0][lrow]=av.x; As[lcol+1][lrow]=av.y; As[lcol+2][lrow]=av.z; As[lcol+3][lrow]=av.w;
        Ws[lcol+0][lrow]=wv.x; Ws[lcol+1][lrow]=wv.y; Ws[lcol+2][lrow]=wv.z; Ws[lcol+3][lrow]=wv.w;
        __syncthreads();
        #pragma unroll
        for (int kk = 0; kk < 16; kk++) {
            float4 a4 = *(const float4*)&As[kk][ty*4];
            float4 w4 = *(const float4*)&Ws[kk][tx*4];
            acc[0][0]+=a4.x*w4.x; acc[0][1]+=a4.x*w4.y; acc[0][2]+=a4.x*w4.z; acc[0][3]+=a4.x*w4.w;
            acc[1][0]+=a4.y*w4.x; acc[1][1]+=a4.y*w4.y; acc[1][2]+=a4.y*w4.z; acc[1][3]+=a4.y*w4.w;
            acc[2][0]+=a4.z*w4.x; acc[2][1]+=a4.z*w4.y; acc[2][2]+=a4.z*w4.z; acc[2][3]+=a4.z*w4.w;
            acc[3][0]+=a4.w*w4.x; acc[3][1]+=a4.w*w4.y; acc[3][2]+=a4.w*w4.z; acc[3][3]+=a4.w*w4.w;
        }
        __syncthreads();
    }
    #pragma unroll
    for (int i = 0; i < 4; i++) {
        long row = bm + ty * 4 + i;
        #pragma unroll
        for (int j = 0; j < 4; j++) {
            int col = bn + tx * 4 + j;
            if (col < N) {
                float v = acc[i][j];
                if (bias) v += bias[col];
                if (res)  v += res[row * (size_t)N + col];
                if (act)  v = fmaxf(v, 0.f);
                C[row * (size_t)N + col] = v;
            }
        }
    }
}

// ---------------- depthwise causal conv (k=4) + silu, fp16 in/out ----------
__global__ void k_dwconv(const float* __restrict__ w, const float* __restrict__ bias)
{
    int b  = blockIdx.y;
    int l0 = blockIdx.x * 16;
    int d  = threadIdx.x;
    float w0 = w[d*4+0], w1 = w[d*4+1], w2 = w[d*4+2], w3 = w[d*4+3];
    float bb = bias[d];
    const __half* xp = g_xz16 + (size_t)b * Lsz * 512 + d;
    float v[19];
    #pragma unroll
    for (int j = 0; j < 19; j++) {
        int ls = l0 + j - 3;
        v[j] = (ls >= 0) ? __half2float(xp[(size_t)ls * 512]) : 0.f;
    }
    __half* op = g_xc16 + ((size_t)b * Lsz + l0) * DI + d;
    #pragma unroll
    for (int t = 0; t < 16; t++) {
        float a = v[t]*w0 + v[t+1]*w1 + v[t+2]*w2 + v[t+3]*w3 + bb;
        op[(size_t)t * DI] = __float2half_rn(a / (1.f + __expf(-a)));
    }
}

// ================= chunked selective scan (3-pass) ==========================
__device__ __forceinline__ void dt_smem(const float* __restrict__ row,
                                        float4 w0, float4 w1, float bd,
                                        float& dt, float& p)
{
    float4 r0 = *(const float4*)(row);
    float4 r1 = *(const float4*)(row + 4);
    float aa = bd + r0.x*w0.x + r0.y*w0.y + r0.z*w0.z + r0.w*w0.w
                  + r1.x*w1.x + r1.y*w1.y + r1.z*w1.z + r1.w*w1.w;
    float e = __expf(aa);
    p  = __fdividef(1.f, 1.f + e);
    dt = (aa > 15.f) ? aa : -__logf(p);
}

__global__ void __launch_bounds__(256)
k_scanA(const float* __restrict__ Alog,
        const float* __restrict__ dtw, const float* __restrict__ dtb)
{
    __shared__ float sdbl[CLEN * 40];
    int c = blockIdx.x, b = blockIdx.y, d = threadIdx.x;

    const float* gsrc = g_dbl + ((size_t)b * Lsz + c * CLEN) * 40;
    for (int i = d; i < CLEN * 40 / 4; i += 256)
        ((float4*)sdbl)[i] = ((const float4*)gsrc)[i];

    float4 w0 = ((const float4*)(dtw + d * 8))[0];
    float4 w1 = ((const float4*)(dtw + d * 8))[1];
    float bd = dtb[d];

    bool fast = true;
    float a[DS];
    #pragma unroll
    for (int s = 0; s < DS; s++) {
        a[s] = -expf(Alog[d * DS + s]);
        if (fabsf(a[s] + (float)(s + 1)) > 1e-4f * (float)(s + 1)) fast = false;
    }
    float h[DS];
    #pragma unroll
    for (int s = 0; s < DS; s++) h[s] = 0.f;
    float sumdt = 0.f;

    const __half* up = g_xc16 + ((size_t)b * Lsz + c * CLEN) * DI + d;
    __syncthreads();

    if (fast) {
        for (int l = 0; l < CLEN; l++) {
            const float* row = sdbl + l * 40;
            float dt, p;
            dt_smem(row, w0, w1, bd, dt, p);
            float w = dt * __half2float(up[(size_t)l * DI]);
            sumdt += dt;
            const float4* B4 = (const float4*)(row + 8);
            float p2 = p * p;
            float q1 = p, q2 = p2, q3 = p2 * p, q4 = p2 * p2;
            float base = 1.f;
            #pragma unroll
            for (int g = 0; g < 4; g++) {
                float4 Bv = B4[g];
                h[4*g+0] = (base*q1)*h[4*g+0] + w*Bv.x;
                h[4*g+1] = (base*q2)*h[4*g+1] + w*Bv.y;
                h[4*g+2] = (base*q3)*h[4*g+2] + w*Bv.z;
                h[4*g+3] = (base*q4)*h[4*g+3] + w*Bv.w;
                base = base * q4;
            }
        }
    } else {
        for (int l = 0; l < CLEN; l++) {
            const float* row = sdbl + l * 40;
            float dt, p;
            dt_smem(row, w0, w1, bd, dt, p);
            float w = dt * __half2float(up[(size_t)l * DI]);
            sumdt += dt;
            #pragma unroll
            for (int s = 0; s < DS; s++) {
                float dA = __expf(dt * a[s]);
                h[s] = dA * h[s] + w * row[8 + s];
            }
        }
    }
    float* slot = g_hc + (((size_t)b * NCH + c) * DI + d) * DS;
    #pragma unroll
    for (int q = 0; q < 4; q++)
        ((float4*)slot)[q] = make_float4(h[4*q], h[4*q+1], h[4*q+2], h[4*q+3]);
    g_sd[((size_t)b * NCH + c) * DI + d] = sumdt;
}

__global__ void __launch_bounds__(256)
k_scanB(const float* __restrict__ Alog)
{
    int b = blockIdx.x, d = threadIdx.x;
    bool fast = true;
    float a[DS];
    #pragma unroll
    for (int s = 0; s < DS; s++) {
        a[s] = -expf(Alog[d * DS + s]);
        if (fabsf(a[s] + (float)(s + 1)) > 1e-4f * (float)(s + 1)) fast = false;
    }
    float hp[DS];
    #pragma unroll
    for (int s = 0; s < DS; s++) hp[s] = 0.f;

    for (int c = 0; c < NCH; c++) {
        float* slot = g_hc + (((size_t)b * NCH + c) * DI + d) * DS;
        float sd = g_sd[((size_t)b * NCH + c) * DI + d];
        float hl[DS];
        #pragma unroll
        for (int q = 0; q < 4; q++) {
            float4 v = ((const float4*)slot)[q];
            hl[4*q] = v.x; hl[4*q+1] = v.y; hl[4*q+2] = v.z; hl[4*q+3] = v.w;
        }
        #pragma unroll
        for (int q = 0; q < 4; q++)
            ((float4*)slot)[q] = make_float4(hp[4*q], hp[4*q+1], hp[4*q+2], hp[4*q+3]);
        if (fast) {
            // exp(a_s*sd) = P^(s+1), P = exp(-sd): 1 MUFU + power-group muls
            float P = __expf(-sd);
            float P2 = P * P;
            float q1 = P, q2 = P2, q3 = P2 * P, q4 = P2 * P2;
            float base = 1.f;
            #pragma unroll
            for (int g = 0; g < 4; g++) {
                hp[4*g+0] = (base*q1)*hp[4*g+0] + hl[4*g+0];
                hp[4*g+1] = (base*q2)*hp[4*g+1] + hl[4*g+1];
                hp[4*g+2] = (base*q3)*hp[4*g+2] + hl[4*g+2];
                hp[4*g+3] = (base*q4)*hp[4*g+3] + hl[4*g+3];
                base = base * q4;
            }
        } else {
            #pragma unroll
            for (int s = 0; s < DS; s++)
                hp[s] = __expf(a[s] * sd) * hp[s] + hl[s];
        }
    }
}

__global__ void __launch_bounds__(256)
k_scanC(const float* __restrict__ Alog,
        const float* __restrict__ dtw, const float* __restrict__ dtb,
        const float* __restrict__ Dp)
{
    __shared__ float sdbl[CLEN * 40];
    int c = blockIdx.x, b = blockIdx.y, d = threadIdx.x;

    const float* gsrc = g_dbl + ((size_t)b * Lsz + c * CLEN) * 40;
    for (int i = d; i < CLEN * 40 / 4; i += 256)
        ((float4*)sdbl)[i] = ((const float4*)gsrc)[i];

    float4 w0 = ((const float4*)(dtw + d * 8))[0];
    float4 w1 = ((const float4*)(dtw + d * 8))[1];
    float bd = dtb[d];
    float Dv = Dp[d];

    bool fast = true;
    float a[DS];
    #pragma unroll
    for (int s = 0; s < DS; s++) {
        a[s] = -expf(Alog[d * DS + s]);
        if (fabsf(a[s] + (float)(s + 1)) > 1e-4f * (float)(s + 1)) fast = false;
    }
    float h[DS];
    const float* slot = g_hc + (((size_t)b * NCH + c) * DI + d) * DS;
    #pragma unroll
    for (int q = 0; q < 4; q++) {
        float4 v = ((const float4*)slot)[q];
        h[4*q] = v.x; h[4*q+1] = v.y; h[4*q+2] = v.z; h[4*q+3] = v.w;
    }

    const __half* up = g_xc16 + ((size_t)b * Lsz + c * CLEN) * DI + d;
    const __half* zp = g_xz16 + ((size_t)b * Lsz + c * CLEN) * 512 + 256 + d;
    __half*       yp = g_y16  + ((size_t)b * Lsz + c * CLEN) * DI + d;
    __syncthreads();

    if (fast) {
        for (int l = 0; l < CLEN; l++) {
            const float* row = sdbl + l * 40;
            float dt, p;
            dt_smem(row, w0, w1, bd, dt, p);
            float u = __half2float(up[(size_t)l * DI]);
            float z = __half2float(zp[(size_t)l * 512]);
            float w = dt * u;
            const float4* B4 = (const float4*)(row + 8);
            const float4* C4 = (const float4*)(row + 24);
            float p2 = p * p;
            float q1 = p, q2 = p2, q3 = p2 * p, q4 = p2 * p2;
            float y0 = 0.f, y1 = 0.f, y2 = 0.f, y3 = 0.f;
            float base = 1.f;
            #pragma unroll
            for (int g = 0; g < 4; g++) {
                float4 Bv = B4[g], Cv = C4[g];
                h[4*g+0] = (base*q1)*h[4*g+0] + w*Bv.x;
                h[4*g+1] = (base*q2)*h[4*g+1] + w*Bv.y;
                h[4*g+2] = (base*q3)*h[4*g+2] + w*Bv.z;
                h[4*g+3] = (base*q4)*h[4*g+3] + w*Bv.w;
                y0 += h[4*g+0]*Cv.x;
                y1 += h[4*g+1]*Cv.y;
                y2 += h[4*g+2]*Cv.z;
                y3 += h[4*g+3]*Cv.w;
                base = base * q4;
            }
            float y = (y0 + y1) + (y2 + y3);
            float sz = __fdividef(z, 1.f + __expf(-z));
            yp[(size_t)l * DI] = __float2half_rn((y + u * Dv) * sz);
        }
    } else {
        for (int l = 0; l < CLEN; l++) {
            const float* row = sdbl + l * 40;
            float dt, p;
            dt_smem(row, w0, w1, bd, dt, p);
            float u = __half2float(up[(size_t)l * DI]);
            float z = __half2float(zp[(size_t)l * 512]);
            float w = dt * u;
            float yacc = 0.f;
            #pragma unroll
            for (int s = 0; s < DS; s++) {
                float dA = __expf(dt * a[s]);
                h[s] = dA * h[s] + w * row[8 + s];
                yacc += h[s] * row[24 + s];
            }
            float sz = __fdividef(z, 1.f + __expf(-z));
            yp[(size_t)l * DI] = __float2half_rn((yacc + u * Dv) * sz);
        }
    }
}

// ---------------- masked mean pool: 2-stage ---------------------------------
__global__ void k_pool1(const float* __restrict__ mask)
{
    int b = blockIdx.x, s = blockIdx.y;
    int e = threadIdx.x;
    const float* xp = g_x + ((size_t)b * Lsz + s * 128) * DM + e;
    const float* mp = mask + (size_t)b * Lsz + s * 128;
    float acc = 0.f, ms = 0.f;
    for (int l = 0; l < 128; l++) {
        float m = mp[l];
        acc += xp[(size_t)l * DM] * m;
        ms += m;
    }
    g_poolp[(b * 16 + s) * DM + e] = acc;
    if (e == 0) g_msum[b * 16 + s] = ms;
}
__global__ void k_pool2()
{
    int b = blockIdx.x, e = threadIdx.x;
    float acc = 0.f, ms = 0.f;
    for (int s = 0; s < 16; s++) {
        acc += g_poolp[(b * 16 + s) * DM + e];
        ms += g_msum[b * 16 + s];
    }
    g_pool[b * DM + e] = acc / fmaxf(ms, 1e-9f);
}

__global__ void k_mlp3(const float* __restrict__ w, const float* __restrict__ bias,
                       float* __restrict__ out)
{
    int t = threadIdx.x;
    if (t >= Bsz * 3) return;
    int bb = t / 3, n = t - bb * 3;
    const float* hp = g_h2 + bb * 512;
    const float* wp = w + n * 512;
    float acc = bias[n];
    for (int k = 0; k < 512; k++) acc += hp[k] * wp[k];
    out[bb * 3 + n] = acc;
}

// ---------------- launch ----------------------------------------------------
extern "C" void kernel_launch(void* const* d_in, const int* in_sizes, int n_in,
                              void* d_out, int out_size)
{
    const int*   tokens = (const int*)  d_in[0];
    const float* mask   = (const float*)d_in[1];
    const float* emb    = (const float*)d_in[2];
    const float* bn_w   = (const float*)d_in[3];
    const float* bn_b   = (const float*)d_in[4];
    const float* conv_w = (const float*)d_in[5];
    const float* conv_b = (const float*)d_in[6];
    const float* in_w   = (const float*)d_in[7];
    const float* c1_w   = (const float*)d_in[8];
    const float* c1_b   = (const float*)d_in[9];
    const float* xp_w   = (const float*)d_in[10];
    const float* dtp_w  = (const float*)d_in[11];
    const float* dtp_b  = (const float*)d_in[12];
    const float* A_log  = (const float*)d_in[13];
    const float* D_p    = (const float*)d_in[14];
    const float* out_w  = (const float*)d_in[15];
    const float* norm_w = (const float*)d_in[16];
    const float* l1w    = (const float*)d_in[17];
    const float* l1b    = (const float*)d_in[18];
    const float* l2w    = (const float*)d_in[19];
    const float* l2b    = (const float*)d_in[20];
    const float* l3w    = (const float*)d_in[21];
    const float* l3b    = (const float*)d_in[22];
    float* out = (float*)d_out;

    float *p_x, *p_dbl, *p_pool, *p_h1, *p_h2;
    __half *p_xn16, *p_xr16, *p_xz16, *p_xc16, *p_y16, *p_wext16, *p_inw16, *p_xpw16, *p_outw16;
    cudaGetSymbolAddress((void**)&p_xn16,  g_xn16);
    cudaGetSymbolAddress((void**)&p_x,     g_x);
    cudaGetSymbolAddress((void**)&p_xr16,  g_xr16);
    cudaGetSymbolAddress((void**)&p_xz16,  g_xz16);
    cudaGetSymbolAddress((void**)&p_xc16,  g_xc16);
    cudaGetSymbolAddress((void**)&p_dbl,   g_dbl);
    cudaGetSymbolAddress((void**)&p_y16,   g_y16);
    cudaGetSymbolAddress((void**)&p_pool,  g_pool);
    cudaGetSymbolAddress((void**)&p_h1,    g_h1);
    cudaGetSymbolAddress((void**)&p_h2,    g_h2);
    cudaGetSymbolAddress((void**)&p_wext16,g_wext16);
    cudaGetSymbolAddress((void**)&p_inw16, g_inw16);
    cudaGetSymbolAddress((void**)&p_xpw16, g_xpw16);
    cudaGetSymbolAddress((void**)&p_outw16,g_outw16);

    const int SMB = 98304;  // 3 x (A 16K | B 16K)
    cudaFuncSetAttribute(k_hmm<0,false,false>, cudaFuncAttributeMaxDynamicSharedMemorySize, SMB);
    cudaFuncSetAttribute(k_hmm<0,false,true>,  cudaFuncAttributeMaxDynamicSharedMemorySize, SMB);
    cudaFuncSetAttribute(k_hmm<0,true,false>,  cudaFuncAttributeMaxDynamicSharedMemorySize, SMB);
    cudaFuncSetAttribute(k_hmm<2,false,true>,  cudaFuncAttributeMaxDynamicSharedMemorySize, SMB);

    // weight conversions (tiny)
    k_cvtw<<<(NL*512*DM + 255)/256, 256>>>(in_w, norm_w, p_inw16);
    k_cvt<<<(NL*40*DI  + 255)/256, 256>>>(xp_w,  p_xpw16,  NL*40*DI);
    k_cvt<<<(NL*DM*DI  + 255)/256, 256>>>(out_w, p_outw16, NL*DM*DI);
    k_repack<<<(DM * 384 + 255) / 256, 256>>>(conv_w);
    k_embed<<<BL * EMBD / 256, 256>>>(tokens, emb, bn_w, bn_b);

    // front conv: implicit GEMM, bias+relu -> g_x; also computes g_rf
    k_hmm<2,false,true><<<dim3(BL / 128, 1), 256, SMB>>>(
        p_xn16, p_wext16, conv_b, (const float*)0,
        p_x, (__half*)0, 384, 128, 128, 128, 1);

    for (int i = 0; i < NL; i++) {
        const float* Al = A_log + (size_t)i * DI * DS;
        const float* dw = dtp_w + (size_t)i * DI * DR;
        const float* db = dtp_b + (size_t)i * DI;

        // normalized fp16 copy of residual (rf from previous GEMM)
        k_normcopy<<<BL / 8, 256>>>();
        // in_proj (norm_w folded into weights) -> g_xz16
        k_hmm<0,true,false><<<dim3(BL / 128, 4), 256, SMB>>>(
            p_xr16, p_inw16 + (size_t)i * 512 * DM, (const float*)0, (const float*)0,
            (float*)0, p_xz16, 128, 512, 512, 512, 0);
        k_dwconv<<<dim3(Lsz / 16, Bsz), 256>>>(c1_w + (size_t)i * DI * 4, c1_b + (size_t)i * DI);
        // x_proj -> g_dbl
        k_hmm<0,false,false><<<dim3(BL / 128, 1), 256, SMB>>>(
            p_xc16, p_xpw16 + (size_t)i * 40 * DI, (const float*)0, (const float*)0,
            p_dbl, (__half*)0, 256, 40, 40, 40, 0);
        k_scanA<<<dim3(NCH, Bsz), 256>>>(Al, dw, db);
        k_scanB<<<Bsz, 256>>>(Al);
        k_scanC<<<dim3(NCH, Bsz), 256>>>(Al, dw, db, D_p + (size_t)i * DI);
        // out_proj: += residual -> g_x; also computes g_rf
        k_hmm<0,false,true><<<dim3(BL / 128, 1), 256, SMB>>>(
            p_y16, p_outw16 + (size_t)i * DM * DI, (const float*)0, p_x,
            p_x, (__half*)0, 256, 128, 128, 128, 0);
    }

    k_pool1<<<dim3(Bsz, 16), 128>>>(mask);
    k_pool2<<<Bsz, 128>>>();
    k_gemm<<<dim3(1, 512 / 64), 256>>>(p_pool, l1w, l1b, (const float*)0, p_h1, 512, DM, 1);
    k_gemm<<<dim3(1, 512 / 64), 256>>>(p_h1,   l2w, l2b, (const float*)0, p_h2, 512, 512, 1);
    k_mlp3<<<1, 256>>>(l3w, l3b, out);
}

// round 16
// speedup vs baseline: 1.0318x; 1.0180x over previous
#include <cuda_runtime.h>
#include <cuda_fp16.h>
#include <math.h>
#include <stdint.h>

#define Bsz 64
#define Lsz 2048
#define BL (Bsz*Lsz)      // 131072
#define EMBD 128
#define DM 128
#define DI 256
#define DS 16
#define DR 8
#define NL 4
#define NCH 32            // scan chunks
#define CLEN 64           // chunk length

// ---------------- scratch (static device arrays; no cudaMalloc) ------------
__device__ __half g_xn16[BL*DM];         // embed output fp16 (front conv input)
__device__ float  g_x [BL*DM];           // residual stream (fp32)
__device__ float  g_rf[BL];              // rmsnorm scale factor per row
__device__ __half g_xr16[BL*DM];         // fp16(g_x * rf)  (in_proj input)
__device__ __half g_xz16[(size_t)BL*512];// in_proj out fp16: [..:256]=xi, [256:]=z
__device__ __half g_xc16[(size_t)BL*DI]; // depthwise conv + silu = u (fp16)
__device__ float  g_dbl[(size_t)BL*40];  // x_proj out (dtlow|B|C) fp32
__device__ __half g_y16[(size_t)BL*DI];  // gated scan out (fp16)
__device__ float  g_hc[(size_t)Bsz*NCH*DI*DS]; // chunk states
__device__ float  g_sd[(size_t)Bsz*NCH*DI];    // chunk sum(dt)
__device__ __half g_wext16[DM*384];      // repacked front conv weight fp16
__device__ __half g_inw16[NL*512*DM];    // in_proj weights fp16 (norm_w folded)
__device__ __half g_xpw16[NL*40*DI];     // x_proj weights fp16
__device__ __half g_outw16[NL*DM*DI];    // out_proj weights fp16
__device__ float  g_pool[Bsz*DM];
__device__ float  g_poolp[Bsz*16*DM];
__device__ float  g_msum[Bsz*16];
__device__ float  g_h1[Bsz*512];
__device__ float  g_h2[Bsz*512];

// =================== helpers ===============================================
__device__ __forceinline__ uint32_t s2u(const void* p) {
    uint32_t a;
    asm("{ .reg .u64 t; cvta.to.shared.u64 t, %1; cvt.u32.u64 %0, t; }" : "=r"(a) : "l"(p));
    return a;
}
__device__ __forceinline__ uint32_t swz(uint32_t off) {   // SW128 swizzle
    return off ^ ((off >> 3) & 0x70);
}
__device__ __forceinline__ void ldm_x4(uint32_t* r, uint32_t addr) {
    asm volatile("ldmatrix.sync.aligned.m8n8.x4.shared.b16 {%0,%1,%2,%3}, [%4];"
        : "=r"(r[0]), "=r"(r[1]), "=r"(r[2]), "=r"(r[3]) : "r"(addr));
}
__device__ __forceinline__ void mma_f16(float* d, const uint32_t* a, const uint32_t* b) {
    asm volatile(
        "mma.sync.aligned.m16n8k16.row.col.f32.f16.f16.f32 "
        "{%0,%1,%2,%3}, {%4,%5,%6,%7}, {%8,%9}, {%0,%1,%2,%3};"
        : "+f"(d[0]), "+f"(d[1]), "+f"(d[2]), "+f"(d[3])
        : "r"(a[0]), "r"(a[1]), "r"(a[2]), "r"(a[3]), "r"(b[0]), "r"(b[1]));
}
__device__ __forceinline__ void cpa16(uint32_t dst, const void* src, int sz) {
    asm volatile("cp.async.cg.shared.global [%0], [%1], 16, %2;"
        :: "r"(dst), "l"(src), "r"(sz));
}
#define CPA_COMMIT() asm volatile("cp.async.commit_group;" ::: "memory")
#define CPA_WAIT1()  asm volatile("cp.async.wait_group 1;" ::: "memory")

// ============== cp.async pipelined fp16 GEMM via mma.sync ===================
// block tile 128x128, K-chunk 64, 3-stage cp.async pipeline.
// AMODE: 0 = plain fp16 A; 2 = front conv (A16=g_xn16, shifted rows)
// CHALF: store C fp16; WRF: rmsnorm factor of output rows -> g_rf
template<int AMODE, bool CHALF, bool WRF>
__global__ void __launch_bounds__(256, 2)
k_hmm(const __half* __restrict__ A16, const __half* __restrict__ W16,
      const float* __restrict__ bias, const float* __restrict__ res,
      float* __restrict__ C, __half* __restrict__ C16,
      int K, int ldC, int Nreal, int Nstore, int relu)
{
    constexpr int STG = 32768;     // A 16K | B 16K per stage, 3 stages
    extern __shared__ char smem[];
    __shared__ float rsum[128];
    uint32_t sbase = s2u(smem);

    int tid = threadIdx.x;
    int wid = tid >> 5, lane = tid & 31;
    int mw = wid & 3, nw = wid >> 2;          // 4 x 2 warp grid
    long bm = (long)blockIdx.x * 128;
    int bn = blockIdx.y * 128;

    int lmat = lane >> 3, lrow = lane & 7;
    int a_row = mw * 32 + (lmat & 1) * 8 + lrow;
    int a_koff = (lmat >> 1) * 16;
    int b_row = nw * 64 + (lmat >> 1) * 8 + lrow;
    int b_koff = (lmat & 1) * 16;

    bool wact = (bn + nw * 64) < Nreal;
    int KB = K / 64;

    float acc[2][8][4];
    #pragma unroll
    for (int f = 0; f < 2; f++)
        #pragma unroll
        for (int n = 0; n < 8; n++)
            #pragma unroll
            for (int j = 0; j < 4; j++) acc[f][n][j] = 0.f;

    auto ISSUE = [&](int st) {
        if (st >= KB) return;
        uint32_t abuf = sbase + (st % 3) * STG;
        uint32_t bbuf = abuf + 16384;
        #pragma unroll
        for (int j = 0; j < 4; j++) {
            int c = j * 256 + tid;
            int r = c >> 3, ch = c & 7;
            uint32_t dst = abuf + swz((uint32_t)(r * 128 + ch * 16));
            const __half* src;
            int sz = 16;
            if constexpr (AMODE == 0) {
                src = A16 + (size_t)(bm + r) * K + st * 64 + ch * 8;
            } else {
                int tap = st >> 1;
                int e = (st & 1) * 64 + ch * 8;
                long m = bm + r;
                int l = (int)(m & (Lsz - 1));
                int lsrc = l + tap - 1;
                src = A16 + (size_t)(m + tap - 1) * 128 + e;
                if (lsrc < 0 || lsrc >= Lsz) sz = 0;
            }
            cpa16(dst, src, sz);
        }
        #pragma unroll
        for (int j = 0; j < 4; j++) {
            int c = j * 256 + tid;
            int n = c >> 3, ch = c & 7;
            uint32_t dst = bbuf + swz((uint32_t)(n * 128 + ch * 16));
            const __half* src = W16 + (size_t)(bn + n) * K + st * 64 + ch * 8;
            int sz = (bn + n < Nreal) ? 16 : 0;
            cpa16(dst, src, sz);
        }
    };

    ISSUE(0); CPA_COMMIT();
    ISSUE(1); CPA_COMMIT();

    for (int kb = 0; kb < KB; kb++) {
        CPA_WAIT1();
        __syncthreads();
        if (wact) {
            uint32_t abuf = sbase + (kb % 3) * STG;
            uint32_t bbuf = abuf + 16384;
            #pragma unroll
            for (int kk = 0; kk < 4; kk++) {
                uint32_t ah[2][4];
                #pragma unroll
                for (int f = 0; f < 2; f++) {
                    uint32_t sw = swz((uint32_t)((a_row + f * 16) * 128 + kk * 32 + a_koff));
                    ldm_x4(ah[f], abuf + sw);
                }
                #pragma unroll
                for (int np = 0; np < 4; np++) {
                    uint32_t bh[4];
                    uint32_t sw = swz((uint32_t)((b_row + np * 16) * 128 + kk * 32 + b_koff));
                    ldm_x4(bh, bbuf + sw);
                    #pragma unroll
                    for (int f = 0; f < 2; f++) {
                        mma_f16(acc[f][2*np+0], ah[f], bh + 0);
                        mma_f16(acc[f][2*np+1], ah[f], bh + 2);
                    }
                }
            }
        }
        ISSUE(kb + 2);
        CPA_COMMIT();
    }

    if constexpr (WRF) {
        if (tid < 128) rsum[tid] = 0.f;
        __syncthreads();
    }

    int g = lane >> 2, t2 = (lane & 3) * 2;
    #pragma unroll
    for (int f = 0; f < 2; f++) {
        float s0 = 0.f, s1 = 0.f;
        long r0 = bm + mw * 32 + f * 16 + g;
        long r1 = r0 + 8;
        #pragma unroll
        for (int nt = 0; nt < 8; nt++) {
            int col = bn + nw * 64 + nt * 8 + t2;
            if (col >= Nstore) continue;
            float2 d0 = make_float2(acc[f][nt][0], acc[f][nt][1]);
            float2 d1 = make_float2(acc[f][nt][2], acc[f][nt][3]);
            if (bias) { float b0 = bias[col], b1 = bias[col+1];
                        d0.x += b0; d0.y += b1; d1.x += b0; d1.y += b1; }
            if (res) {
                float2 q0 = *(const float2*)(res + (size_t)r0 * ldC + col);
                float2 q1 = *(const float2*)(res + (size_t)r1 * ldC + col);
                d0.x += q0.x; d0.y += q0.y; d1.x += q1.x; d1.y += q1.y;
            }
            if (relu) {
                d0.x = fmaxf(d0.x, 0.f); d0.y = fmaxf(d0.y, 0.f);
                d1.x = fmaxf(d1.x, 0.f); d1.y = fmaxf(d1.y, 0.f);
            }
            if constexpr (WRF) {
                s0 += d0.x * d0.x + d0.y * d0.y;
                s1 += d1.x * d1.x + d1.y * d1.y;
            }
            if constexpr (CHALF) {
                *(__half2*)(C16 + (size_t)r0 * ldC + col) = __floats2half2_rn(d0.x, d0.y);
                *(__half2*)(C16 + (size_t)r1 * ldC + col) = __floats2half2_rn(d1.x, d1.y);
            } else {
                *(float2*)(C + (size_t)r0 * ldC + col) = d0;
                *(float2*)(C + (size_t)r1 * ldC + col) = d1;
            }
        }
        if constexpr (WRF) {
            s0 += __shfl_xor_sync(0xffffffffu, s0, 1);
            s0 += __shfl_xor_sync(0xffffffffu, s0, 2);
            s1 += __shfl_xor_sync(0xffffffffu, s1, 1);
            s1 += __shfl_xor_sync(0xffffffffu, s1, 2);
            if ((lane & 3) == 0) {
                atomicAdd(&rsum[(int)(r0 - bm)], s0);
                atomicAdd(&rsum[(int)(r1 - bm)], s1);
            }
        }
    }
    if constexpr (WRF) {
        __syncthreads();
        if (tid < 128)
            g_rf[bm + tid] = rsqrtf(rsum[tid] * (1.f / DM) + 1e-5f);
    }
}

// ---------------- embed + batchnorm-ish scale -> fp16 ----------------------
__global__ void k_embed(const int* __restrict__ tok, const float* __restrict__ emb,
                        const float* __restrict__ bnw, const float* __restrict__ bnb)
{
    int idx = blockIdx.x * 256 + threadIdx.x;
    if (idx >= BL * EMBD) return;
    int e = idx & 127;
    int t = idx >> 7;
    float s = bnw[e] * rsqrtf(1.0f + 1e-5f);
    g_xn16[idx] = __float2half_rn(emb[tok[t] * EMBD + e] * s + bnb[e]);
}

__global__ void k_repack(const float* __restrict__ cw)
{
    int idx = blockIdx.x * 256 + threadIdx.x;
    if (idx >= DM * 384) return;
    int o = idx / 384, kg = idx % 384;
    int tap = kg >> 7, e = kg & 127;
    g_wext16[idx] = __float2half_rn(cw[(o * EMBD + e) * 3 + tap]);
}

__global__ void k_cvt(const float* __restrict__ src, __half* __restrict__ dst, int n)
{
    int i = blockIdx.x * 256 + threadIdx.x;
    if (i < n) dst[i] = __float2half_rn(src[i]);
}

// in_proj weights with norm_w folded (per layer)
__global__ void k_cvtw(const float* __restrict__ w, const float* __restrict__ nw,
                       __half* __restrict__ dst)
{
    int i = blockIdx.x * 256 + threadIdx.x;
    if (i >= NL * 512 * DM) return;
    int k = i & 127;
    int layer = i / (512 * DM);
    dst[i] = __float2half_rn(w[i] * nw[layer * DM + k]);
}

// g_xr16 = fp16(g_x * rf)
__global__ void k_normcopy()
{
    long idx4 = (long)blockIdx.x * 256 + threadIdx.x;   // BL*128/4 float4s
    float4 v = ((const float4*)g_x)[idx4];
    float rf = g_rf[idx4 >> 5];
    __half2* o = (__half2*)g_xr16 + idx4 * 2;
    o[0] = __floats2half2_rn(v.x * rf, v.y * rf);
    o[1] = __floats2half2_rn(v.z * rf, v.w * rf);
}

// ---------------- generic fp32 GEMM (small head layers) --------------------
__global__ void k_gemm(const float* __restrict__ A, const float* __restrict__ W,
                       const float* __restrict__ bias, const float* __restrict__ res,
                       float* __restrict__ C, int N, int K, int act)
{
    __shared__ float As[16][64];
    __shared__ float Ws[16][64];
    int tid = threadIdx.x;
    int tx = tid & 15, ty = tid >> 4;
    long bm = (long)blockIdx.x * 64;
    int bn = blockIdx.y * 64;
    int lrow = tid >> 2, lcol = (tid & 3) * 4;
    const float* Ap = A + (bm + lrow) * (size_t)K + lcol;
    int nrow = bn + lrow;
    const float* Wp = (nrow < N) ? (W + (size_t)nrow * K + lcol) : (const float*)0;
    float acc[4][4] = {};
    for (int kc = 0; kc < K; kc += 16) {
        float4 av = *(const float4*)(Ap + kc);
        float4 wv = make_float4(0.f, 0.f, 0.f, 0.f);
        if (Wp) wv = *(const float4*)(Wp + kc);
        As[lcol+0][lrow]=av.x; As[lcol+1][lrow]=av.y; As[lcol+2][lrow]=av.z; As[lcol+3][lrow]=av.w;
        Ws[lcol+0][lrow]=wv.x; Ws[lcol+1][lrow]=wv.y; Ws[lcol+2][lrow]=wv.z; Ws[lcol+3][lrow]=wv.w;
        __syncthreads();
        #pragma unroll
        for (int kk = 0; kk < 16; kk++) {
            float4 a4 = *(const float4*)&As[kk][ty*4];
            float4 w4 = *(const float4*)&Ws[kk][tx*4];
            acc[0][0]+=a4.x*w4.x; acc[0][1]+=a4.x*w4.y; acc[0][2]+=a4.x*w4.z; acc[0][3]+=a4.x*w4.w;
            acc[1][0]+=a4.y*w4.x; acc[1][1]+=a4.y*w4.y; acc[1][2]+=a4.y*w4.z; acc[1][3]+=a4.y*w4.w;
            acc[2][0]+=a4.z*w4.x; acc[2][1]+=a4.z*w4.y; acc[2][2]+=a4.z*w4.z; acc[2][3]+=a4.z*w4.w;
            acc[3][0]+=a4.w*w4.x; acc[3][1]+=a4.w*w4.y; acc[3][2]+=a4.w*w4.z; acc[3][3]+=a4.w*w4.w;
        }
        __syncthreads();
    }
    #pragma unroll
    for (int i = 0; i < 4; i++) {
        long row = bm + ty * 4 + i;
        #pragma unroll
        for (int j = 0; j < 4; j++) {
            int col = bn + tx * 4 + j;
            if (col < N) {
                float v = acc[i][j];
                if (bias) v += bias[col];
                if (res)  v += res[row * (size_t)N + col];
                if (act)  v = fmaxf(v, 0.f);
                C[row * (size_t)N + col] = v;
            }
        }
    }
}

// ---------------- depthwise causal conv (k=4) + silu, fp16 in/out ----------
__global__ void k_dwconv(const float* __restrict__ w, const float* __restrict__ bias)
{
    int b  = blockIdx.y;
    int l0 = blockIdx.x * 16;
    int d  = threadIdx.x;
    float w0 = w[d*4+0], w1 = w[d*4+1], w2 = w[d*4+2], w3 = w[d*4+3];
    float bb = bias[d];
    const __half* xp = g_xz16 + (size_t)b * Lsz * 512 + d;
    float v[19];
    #pragma unroll
    for (int j = 0; j < 19; j++) {
        int ls = l0 + j - 3;
        v[j] = (ls >= 0) ? __half2float(xp[(size_t)ls * 512]) : 0.f;
    }
    __half* op = g_xc16 + ((size_t)b * Lsz + l0) * DI + d;
    #pragma unroll
    for (int t = 0; t < 16; t++) {
        float a = v[t]*w0 + v[t+1]*w1 + v[t+2]*w2 + v[t+3]*w3 + bb;
        op[(size_t)t * DI] = __float2half_rn(a / (1.f + __expf(-a)));
    }
}

// ================= chunked selective scan (3-pass) ==========================
__device__ __forceinline__ void dt_smem(const float* __restrict__ row,
                                        float4 w0, float4 w1, float bd,
                                        float& dt, float& p)
{
    float4 r0 = *(const float4*)(row);
    float4 r1 = *(const float4*)(row + 4);
    float aa = bd + r0.x*w0.x + r0.y*w0.y + r0.z*w0.z + r0.w*w0.w
                  + r1.x*w1.x + r1.y*w1.y + r1.z*w1.z + r1.w*w1.w;
    float e = __expf(aa);
    p  = __fdividef(1.f, 1.f + e);
    dt = (aa > 15.f) ? aa : -__logf(p);
}

__global__ void __launch_bounds__(256)
k_scanA(const float* __restrict__ Alog,
        const float* __restrict__ dtw, const float* __restrict__ dtb)
{
    __shared__ float sdbl[CLEN * 40];
    int c = blockIdx.x, b = blockIdx.y, d = threadIdx.x;

    const float* gsrc = g_dbl + ((size_t)b * Lsz + c * CLEN) * 40;
    for (int i = d; i < CLEN * 40 / 4; i += 256)
        ((float4*)sdbl)[i] = ((const float4*)gsrc)[i];

    float4 w0 = ((const float4*)(dtw + d * 8))[0];
    float4 w1 = ((const float4*)(dtw + d * 8))[1];
    float bd = dtb[d];

    bool fast = true;
    float a[DS];
    #pragma unroll
    for (int s = 0; s < DS; s++) {
        a[s] = -expf(Alog[d * DS + s]);
        if (fabsf(a[s] + (float)(s + 1)) > 1e-4f * (float)(s + 1)) fast = false;
    }
    float h[DS];
    #pragma unroll
    for (int s = 0; s < DS; s++) h[s] = 0.f;
    float sumdt = 0.f;

    const __half* up = g_xc16 + ((size_t)b * Lsz + c * CLEN) * DI + d;
    __syncthreads();

    if (fast) {
        for (int l = 0; l < CLEN; l++) {
            const float* row = sdbl + l * 40;
            float dt, p;
            dt_smem(row, w0, w1, bd, dt, p);
            float w = dt * __half2float(up[(size_t)l * DI]);
            sumdt += dt;
            const float4* B4 = (const float4*)(row + 8);
            float p2 = p * p;
            float q1 = p, q2 = p2, q3 = p2 * p, q4 = p2 * p2;
            float base = 1.f;
            #pragma unroll
            for (int g = 0; g < 4; g++) {
                float4 Bv = B4[g];
                h[4*g+0] = (base*q1)*h[4*g+0] + w*Bv.x;
                h[4*g+1] = (base*q2)*h[4*g+1] + w*Bv.y;
                h[4*g+2] = (base*q3)*h[4*g+2] + w*Bv.z;
                h[4*g+3] = (base*q4)*h[4*g+3] + w*Bv.w;
                base = base * q4;
            }
        }
    } else {
        for (int l = 0; l < CLEN; l++) {
            const float* row = sdbl + l * 40;
            float dt, p;
            dt_smem(row, w0, w1, bd, dt, p);
            float w = dt * __half2float(up[(size_t)l * DI]);
            sumdt += dt;
            #pragma unroll
            for (int s = 0; s < DS; s++) {
                float dA = __expf(dt * a[s]);
                h[s] = dA * h[s] + w * row[8 + s];
            }
        }
    }
    float* slot = g_hc + (((size_t)b * NCH + c) * DI + d) * DS;
    #pragma unroll
    for (int q = 0; q < 4; q++)
        ((float4*)slot)[q] = make_float4(h[4*q], h[4*q+1], h[4*q+2], h[4*q+3]);
    g_sd[((size_t)b * NCH + c) * DI + d] = sumdt;
}

__global__ void __launch_bounds__(256)
k_scanB(const float* __restrict__ Alog)
{
    int b = blockIdx.x, d = threadIdx.x;
    float a[DS];
    #pragma unroll
    for (int s = 0; s < DS; s++) a[s] = -expf(Alog[d * DS + s]);
    float hp[DS];
    #pragma unroll
    for (int s = 0; s < DS; s++) hp[s] = 0.f;

    for (int c = 0; c < NCH; c++) {
        float* slot = g_hc + (((size_t)b * NCH + c) * DI + d) * DS;
        float sd = g_sd[((size_t)b * NCH + c) * DI + d];
        float hl[DS];
        #pragma unroll
        for (int q = 0; q < 4; q++) {
            float4 v = ((const float4*)slot)[q];
            hl[4*q] = v.x; hl[4*q+1] = v.y; hl[4*q+2] = v.z; hl[4*q+3] = v.w;
        }
        #pragma unroll
        for (int q = 0; q < 4; q++)
            ((float4*)slot)[q] = make_float4(hp[4*q], hp[4*q+1], hp[4*q+2], hp[4*q+3]);
        #pragma unroll
        for (int s = 0; s < DS; s++)
            hp[s] = __expf(a[s] * sd) * hp[s] + hl[s];
    }
}

__global__ void __launch_bounds__(256)
k_scanC(const float* __restrict__ Alog,
        const float* __restrict__ dtw, const float* __restrict__ dtb,
        const float* __restrict__ Dp)
{
    __shared__ float sdbl[CLEN * 40];
    int c = blockIdx.x, b = blockIdx.y, d = threadIdx.x;

    const float* gsrc = g_dbl + ((size_t)b * Lsz + c * CLEN) * 40;
    for (int i = d; i < CLEN * 40 / 4; i += 256)
        ((float4*)sdbl)[i] = ((const float4*)gsrc)[i];

    float4 w0 = ((const float4*)(dtw + d * 8))[0];
    float4 w1 = ((const float4*)(dtw + d * 8))[1];
    float bd = dtb[d];
    float Dv = Dp[d];

    bool fast = true;
    float a[DS];
    #pragma unroll
    for (int s = 0; s < DS; s++) {
        a[s] = -expf(Alog[d * DS + s]);
        if (fabsf(a[s] + (float)(s + 1)) > 1e-4f * (float)(s + 1)) fast = false;
    }
    float h[DS];
    const float* slot = g_hc + (((size_t)b * NCH + c) * DI + d) * DS;
    #pragma unroll
    for (int q = 0; q < 4; q++) {
        float4 v = ((const float4*)slot)[q];
        h[4*q] = v.x; h[4*q+1] = v.y; h[4*q+2] = v.z; h[4*q+3] = v.w;
    }

    const __half* up = g_xc16 + ((size_t)b * Lsz + c * CLEN) * DI + d;
    const __half* zp = g_xz16 + ((size_t)b * Lsz + c * CLEN) * 512 + 256 + d;
    __half*       yp = g_y16  + ((size_t)b * Lsz + c * CLEN) * DI + d;
    __syncthreads();

    if (fast) {
        for (int l = 0; l < CLEN; l++) {
            const float* row = sdbl + l * 40;
            float dt, p;
            dt_smem(row, w0, w1, bd, dt, p);
            float u = __half2float(up[(size_t)l * DI]);
            float z = __half2float(zp[(size_t)l * 512]);
            float w = dt * u;
            const float4* B4 = (const float4*)(row + 8);
            const float4* C4 = (const float4*)(row + 24);
            float p2 = p * p;
            float q1 = p, q2 = p2, q3 = p2 * p, q4 = p2 * p2;
            float y0 = 0.f, y1 = 0.f, y2 = 0.f, y3 = 0.f;
            float base = 1.f;
            #pragma unroll
            for (int g = 0; g < 4; g++) {
                float4 Bv = B4[g], Cv = C4[g];
                h[4*g+0] = (base*q1)*h[4*g+0] + w*Bv.x;
                h[4*g+1] = (base*q2)*h[4*g+1] + w*Bv.y;
                h[4*g+2] = (base*q3)*h[4*g+2] + w*Bv.z;
                h[4*g+3] = (base*q4)*h[4*g+3] + w*Bv.w;
                y0 += h[4*g+0]*Cv.x;
                y1 += h[4*g+1]*Cv.y;
                y2 += h[4*g+2]*Cv.z;
                y3 += h[4*g+3]*Cv.w;
                base = base * q4;
            }
            float y = (y0 + y1) + (y2 + y3);
            float sz = __fdividef(z, 1.f + __expf(-z));
            yp[(size_t)l * DI] = __float2half_rn((y + u * Dv) * sz);
        }
    } else {
        for (int l = 0; l < CLEN; l++) {
            const float* row = sdbl + l * 40;
            float dt, p;
            dt_smem(row, w0, w1, bd, dt, p);
            float u = __half2float(up[(size_t)l * DI]);
            float z = __half2float(zp[(size_t)l * 512]);
            float w = dt * u;
            float yacc = 0.f;
            #pragma unroll
            for (int s = 0; s < DS; s++) {
                float dA = __expf(dt * a[s]);
                h[s] = dA * h[s] + w * row[8 + s];
                yacc += h[s] * row[24 + s];
            }
            float sz = __fdividef(z, 1.f + __expf(-z));
            yp[(size_t)l * DI] = __float2half_rn((yacc + u * Dv) * sz);
        }
    }
}

// ---------------- masked mean pool: 2-stage ---------------------------------
__global__ void k_pool1(const float* __restrict__ mask)
{
    int b = blockIdx.x, s = blockIdx.y;
    int e = threadIdx.x;
    const float* xp = g_x + ((size_t)b * Lsz + s * 128) * DM + e;
    const float* mp = mask + (size_t)b * Lsz + s * 128;
    float acc = 0.f, ms = 0.f;
    for (int l = 0; l < 128; l++) {
        float m = mp[l];
        acc += xp[(size_t)l * DM] * m;
        ms += m;
    }
    g_poolp[(b * 16 + s) * DM + e] = acc;
    if (e == 0) g_msum[b * 16 + s] = ms;
}
__global__ void k_pool2()
{
    int b = blockIdx.x, e = threadIdx.x;
    float acc = 0.f, ms = 0.f;
    for (int s = 0; s < 16; s++) {
        acc += g_poolp[(b * 16 + s) * DM + e];
        ms += g_msum[b * 16 + s];
    }
    g_pool[b * DM + e] = acc / fmaxf(ms, 1e-9f);
}

__global__ void k_mlp3(const float* __restrict__ w, const float* __restrict__ bias,
                       float* __restrict__ out)
{
    int t = threadIdx.x;
    if (t >= Bsz * 3) return;
    int bb = t / 3, n = t - bb * 3;
    const float* hp = g_h2 + bb * 512;
    const float* wp = w + n * 512;
    float acc = bias[n];
    for (int k = 0; k < 512; k++) acc += hp[k] * wp[k];
    out[bb * 3 + n] = acc;
}

// ---------------- launch ----------------------------------------------------
extern "C" void kernel_launch(void* const* d_in, const int* in_sizes, int n_in,
                              void* d_out, int out_size)
{
    const int*   tokens = (const int*)  d_in[0];
    const float* mask   = (const float*)d_in[1];
    const float* emb    = (const float*)d_in[2];
    const float* bn_w   = (const float*)d_in[3];
    const float* bn_b   = (const float*)d_in[4];
    const float* conv_w = (const float*)d_in[5];
    const float* conv_b = (const float*)d_in[6];
    const float* in_w   = (const float*)d_in[7];
    const float* c1_w   = (const float*)d_in[8];
    const float* c1_b   = (const float*)d_in[9];
    const float* xp_w   = (const float*)d_in[10];
    const float* dtp_w  = (const float*)d_in[11];
    const float* dtp_b  = (const float*)d_in[12];
    const float* A_log  = (const float*)d_in[13];
    const float* D_p    = (const float*)d_in[14];
    const float* out_w  = (const float*)d_in[15];
    const float* norm_w = (const float*)d_in[16];
    const float* l1w    = (const float*)d_in[17];
    const float* l1b    = (const float*)d_in[18];
    const float* l2w    = (const float*)d_in[19];
    const float* l2b    = (const float*)d_in[20];
    const float* l3w    = (const float*)d_in[21];
    const float* l3b    = (const float*)d_in[22];
    float* out = (float*)d_out;

    float *p_x, *p_dbl, *p_pool, *p_h1, *p_h2;
    __half *p_xn16, *p_xr16, *p_xz16, *p_xc16, *p_y16, *p_wext16, *p_inw16, *p_xpw16, *p_outw16;
    cudaGetSymbolAddress((void**)&p_xn16,  g_xn16);
    cudaGetSymbolAddress((void**)&p_x,     g_x);
    cudaGetSymbolAddress((void**)&p_xr16,  g_xr16);
    cudaGetSymbolAddress((void**)&p_xz16,  g_xz16);
    cudaGetSymbolAddress((void**)&p_xc16,  g_xc16);
    cudaGetSymbolAddress((void**)&p_dbl,   g_dbl);
    cudaGetSymbolAddress((void**)&p_y16,   g_y16);
    cudaGetSymbolAddress((void**)&p_pool,  g_pool);
    cudaGetSymbolAddress((void**)&p_h1,    g_h1);
    cudaGetSymbolAddress((void**)&p_h2,    g_h2);
    cudaGetSymbolAddress((void**)&p_wext16,g_wext16);
    cudaGetSymbolAddress((void**)&p_inw16, g_inw16);
    cudaGetSymbolAddress((void**)&p_xpw16, g_xpw16);
    cudaGetSymbolAddress((void**)&p_outw16,g_outw16);

    const int SMB = 98304;  // 3 x (A 16K | B 16K)
    cudaFuncSetAttribute(k_hmm<0,false,false>, cudaFuncAttributeMaxDynamicSharedMemorySize, SMB);
    cudaFuncSetAttribute(k_hmm<0,false,true>,  cudaFuncAttributeMaxDynamicSharedMemorySize, SMB);
    cudaFuncSetAttribute(k_hmm<0,true,false>,  cudaFuncAttributeMaxDynamicSharedMemorySize, SMB);
    cudaFuncSetAttribute(k_hmm<2,false,true>,  cudaFuncAttributeMaxDynamicSharedMemorySize, SMB);

    // weight conversions (tiny)
    k_cvtw<<<(NL*512*DM + 255)/256, 256>>>(in_w, norm_w, p_inw16);
    k_cvt<<<(NL*40*DI  + 255)/256, 256>>>(xp_w,  p_xpw16,  NL*40*DI);
    k_cvt<<<(NL*DM*DI  + 255)/256, 256>>>(out_w, p_outw16, NL*DM*DI);
    k_repack<<<(DM * 384 + 255) / 256, 256>>>(conv_w);
    k_embed<<<BL * EMBD / 256, 256>>>(tokens, emb, bn_w, bn_b);

    // front conv: implicit GEMM, bias+relu -> g_x; also computes g_rf
    k_hmm<2,false,true><<<dim3(BL / 128, 1), 256, SMB>>>(
        p_xn16, p_wext16, conv_b, (const float*)0,
        p_x, (__half*)0, 384, 128, 128, 128, 1);

    for (int i = 0; i < NL; i++) {
        const float* Al = A_log + (size_t)i * DI * DS;
        const float* dw = dtp_w + (size_t)i * DI * DR;
        const float* db = dtp_b + (size_t)i * DI;

        // normalized fp16 copy of residual (rf from previous GEMM)
        k_normcopy<<<BL / 8, 256>>>();
        // in_proj (norm_w folded into weights) -> g_xz16
        k_hmm<0,true,false><<<dim3(BL / 128, 4), 256, SMB>>>(
            p_xr16, p_inw16 + (size_t)i * 512 * DM, (const float*)0, (const float*)0,
            (float*)0, p_xz16, 128, 512, 512, 512, 0);
        k_dwconv<<<dim3(Lsz / 16, Bsz), 256>>>(c1_w + (size_t)i * DI * 4, c1_b + (size_t)i * DI);
        // x_proj -> g_dbl
        k_hmm<0,false,false><<<dim3(BL / 128, 1), 256, SMB>>>(
            p_xc16, p_xpw16 + (size_t)i * 40 * DI, (const float*)0, (const float*)0,
            p_dbl, (__half*)0, 256, 40, 40, 40, 0);
        k_scanA<<<dim3(NCH, Bsz), 256>>>(Al, dw, db);
        k_scanB<<<Bsz, 256>>>(Al);
        k_scanC<<<dim3(NCH, Bsz), 256>>>(Al, dw, db, D_p + (size_t)i * DI);
        // out_proj: += residual -> g_x; also computes g_rf
        k_hmm<0,false,true><<<dim3(BL / 128, 1), 256, SMB>>>(
            p_y16, p_outw16 + (size_t)i * DM * DI, (const float*)0, p_x,
            p_x, (__half*)0, 256, 128, 128, 128, 0);
    }

    k_pool1<<<dim3(Bsz, 16), 128>>>(mask);
    k_pool2<<<Bsz, 128>>>();
    k_gemm<<<dim3(1, 512 / 64), 256>>>(p_pool, l1w, l1b, (const float*)0, p_h1, 512, DM, 1);
    k_gemm<<<dim3(1, 512 / 64), 256>>>(p_h1,   l2w, l2b, (const float*)0, p_h2, 512, 512, 1);
    k_mlp3<<<1, 256>>>(l3w, l3b, out);
}

// round 17
// speedup vs baseline: 1.0643x; 1.0316x over previous
#include <cuda_runtime.h>
#include <cuda_fp16.h>
#include <math.h>
#include <stdint.h>

#define Bsz 64
#define Lsz 2048
#define BL (Bsz*Lsz)      // 131072
#define EMBD 128
#define DM 128
#define DI 256
#define DS 16
#define DR 8
#define NL 4
#define NCH 32            // scan chunks
#define CLEN 64           // chunk length

// ---------------- scratch (static device arrays; no cudaMalloc) ------------
__device__ __half g_xn16[BL*DM];         // embed output fp16 (front conv input)
__device__ float  g_x [BL*DM];           // residual stream (fp32)
__device__ float  g_rf[BL];              // rmsnorm scale factor per row
__device__ __half g_xr16[BL*DM];         // fp16(g_x * rf)  (in_proj input)
__device__ __half g_xz16[(size_t)BL*512];// in_proj out fp16: [..:256]=xi, [256:]=z
__device__ __half g_xc16[(size_t)BL*DI]; // depthwise conv + silu = u (fp16)
__device__ float  g_dbl[(size_t)BL*40];  // x_proj out (dtlow|B|C) fp32
__device__ __half g_y16[(size_t)BL*DI];  // gated scan out (fp16)
__device__ float  g_hc[(size_t)Bsz*NCH*DI*DS]; // chunk states
__device__ float  g_sd[(size_t)Bsz*NCH*DI];    // chunk sum(dt)
__device__ __half g_wext16[DM*384];      // repacked front conv weight fp16
__device__ __half g_inw16[NL*512*DM];    // in_proj weights fp16 (norm_w folded)
__device__ __half g_xpw16[NL*40*DI];     // x_proj weights fp16
__device__ __half g_outw16[NL*DM*DI];    // out_proj weights fp16
__device__ float  g_pool[Bsz*DM];
__device__ float  g_poolp[Bsz*16*DM];
__device__ float  g_msum[Bsz*16];
__device__ float  g_h1[Bsz*512];
__device__ float  g_h2[Bsz*512];

// =================== helpers ===============================================
typedef unsigned long long ull;
__device__ __forceinline__ uint32_t s2u(const void* p) {
    uint32_t a;
    asm("{ .reg .u64 t; cvta.to.shared.u64 t, %1; cvt.u32.u64 %0, t; }" : "=r"(a) : "l"(p));
    return a;
}
__device__ __forceinline__ uint32_t swz(uint32_t off) {   // SW128 swizzle
    return off ^ ((off >> 3) & 0x70);
}
__device__ __forceinline__ void ldm_x4(uint32_t* r, uint32_t addr) {
    asm volatile("ldmatrix.sync.aligned.m8n8.x4.shared.b16 {%0,%1,%2,%3}, [%4];"
        : "=r"(r[0]), "=r"(r[1]), "=r"(r[2]), "=r"(r[3]) : "r"(addr));
}
__device__ __forceinline__ void mma_f16(float* d, const uint32_t* a, const uint32_t* b) {
    asm volatile(
        "mma.sync.aligned.m16n8k16.row.col.f32.f16.f16.f32 "
        "{%0,%1,%2,%3}, {%4,%5,%6,%7}, {%8,%9}, {%0,%1,%2,%3};"
        : "+f"(d[0]), "+f"(d[1]), "+f"(d[2]), "+f"(d[3])
        : "r"(a[0]), "r"(a[1]), "r"(a[2]), "r"(a[3]), "r"(b[0]), "r"(b[1]));
}
__device__ __forceinline__ void cpa16(uint32_t dst, const void* src, int sz) {
    asm volatile("cp.async.cg.shared.global [%0], [%1], 16, %2;"
        :: "r"(dst), "l"(src), "r"(sz));
}
#define CPA_COMMIT() asm volatile("cp.async.commit_group;" ::: "memory")
#define CPA_WAIT1()  asm volatile("cp.async.wait_group 1;" ::: "memory")

// -------- packed f32x2 ops (sm_100-family PTX; 2x fp32 FMA throughput) -----
__device__ __forceinline__ ull pk2(float a, float b) {
    ull r; asm("mov.b64 %0, {%1, %2};" : "=l"(r) : "f"(a), "f"(b)); return r;
}
__device__ __forceinline__ void up2(ull v, float& a, float& b) {
    asm("mov.b64 {%0, %1}, %2;" : "=f"(a), "=f"(b) : "l"(v));
}
__device__ __forceinline__ ull fma2_(ull a, ull b, ull c) {
    ull d; asm("fma.rn.f32x2 %0, %1, %2, %3;" : "=l"(d) : "l"(a), "l"(b), "l"(c)); return d;
}
__device__ __forceinline__ ull mul2_(ull a, ull b) {
    ull d; asm("mul.rn.f32x2 %0, %1, %2;" : "=l"(d) : "l"(a), "l"(b)); return d;
}

// ============== cp.async pipelined fp16 GEMM via mma.sync ===================
// block tile 128x128, K-chunk 64, 3-stage cp.async pipeline.
// AMODE: 0 = plain fp16 A; 2 = front conv (A16=g_xn16, shifted rows)
// CHALF: store C fp16; WRF: rmsnorm factor of output rows -> g_rf
template<int AMODE, bool CHALF, bool WRF>
__global__ void __launch_bounds__(256, 2)
k_hmm(const __half* __restrict__ A16, const __half* __restrict__ W16,
      const float* __restrict__ bias, const float* __restrict__ res,
      float* __restrict__ C, __half* __restrict__ C16,
      int K, int ldC, int Nreal, int Nstore, int relu)
{
    constexpr int STG = 32768;     // A 16K | B 16K per stage, 3 stages
    extern __shared__ char smem[];
    __shared__ float rsum[128];
    uint32_t sbase = s2u(smem);

    int tid = threadIdx.x;
    int wid = tid >> 5, lane = tid & 31;
    int mw = wid & 3, nw = wid >> 2;          // 4 x 2 warp grid
    long bm = (long)blockIdx.x * 128;
    int bn = blockIdx.y * 128;

    int lmat = lane >> 3, lrow = lane & 7;
    int a_row = mw * 32 + (lmat & 1) * 8 + lrow;
    int a_koff = (lmat >> 1) * 16;
    int b_row = nw * 64 + (lmat >> 1) * 8 + lrow;
    int b_koff = (lmat & 1) * 16;

    bool wact = (bn + nw * 64) < Nreal;
    int KB = K / 64;

    float acc[2][8][4];
    #pragma unroll
    for (int f = 0; f < 2; f++)
        #pragma unroll
        for (int n = 0; n < 8; n++)
            #pragma unroll
            for (int j = 0; j < 4; j++) acc[f][n][j] = 0.f;

    auto ISSUE = [&](int st) {
        if (st >= KB) return;
        uint32_t abuf = sbase + (st % 3) * STG;
        uint32_t bbuf = abuf + 16384;
        #pragma unroll
        for (int j = 0; j < 4; j++) {
            int c = j * 256 + tid;
            int r = c >> 3, ch = c & 7;
            uint32_t dst = abuf + swz((uint32_t)(r * 128 + ch * 16));
            const __half* src;
            int sz = 16;
            if constexpr (AMODE == 0) {
                src = A16 + (size_t)(bm + r) * K + st * 64 + ch * 8;
            } else {
                int tap = st >> 1;
                int e = (st & 1) * 64 + ch * 8;
                long m = bm + r;
                int l = (int)(m & (Lsz - 1));
                int lsrc = l + tap - 1;
                src = A16 + (size_t)(m + tap - 1) * 128 + e;
                if (lsrc < 0 || lsrc >= Lsz) sz = 0;
            }
            cpa16(dst, src, sz);
        }
        #pragma unroll
        for (int j = 0; j < 4; j++) {
            int c = j * 256 + tid;
            int n = c >> 3, ch = c & 7;
            uint32_t dst = bbuf + swz((uint32_t)(n * 128 + ch * 16));
            const __half* src = W16 + (size_t)(bn + n) * K + st * 64 + ch * 8;
            int sz = (bn + n < Nreal) ? 16 : 0;
            cpa16(dst, src, sz);
        }
    };

    ISSUE(0); CPA_COMMIT();
    ISSUE(1); CPA_COMMIT();

    for (int kb = 0; kb < KB; kb++) {
        CPA_WAIT1();
        __syncthreads();
        if (wact) {
            uint32_t abuf = sbase + (kb % 3) * STG;
            uint32_t bbuf = abuf + 16384;
            #pragma unroll
            for (int kk = 0; kk < 4; kk++) {
                uint32_t ah[2][4];
                #pragma unroll
                for (int f = 0; f < 2; f++) {
                    uint32_t sw = swz((uint32_t)((a_row + f * 16) * 128 + kk * 32 + a_koff));
                    ldm_x4(ah[f], abuf + sw);
                }
                #pragma unroll
                for (int np = 0; np < 4; np++) {
                    uint32_t bh[4];
                    uint32_t sw = swz((uint32_t)((b_row + np * 16) * 128 + kk * 32 + b_koff));
                    ldm_x4(bh, bbuf + sw);
                    #pragma unroll
                    for (int f = 0; f < 2; f++) {
                        mma_f16(acc[f][2*np+0], ah[f], bh + 0);
                        mma_f16(acc[f][2*np+1], ah[f], bh + 2);
                    }
                }
            }
        }
        ISSUE(kb + 2);
        CPA_COMMIT();
    }

    if constexpr (WRF) {
        if (tid < 128) rsum[tid] = 0.f;
        __syncthreads();
    }

    int g = lane >> 2, t2 = (lane & 3) * 2;
    #pragma unroll
    for (int f = 0; f < 2; f++) {
        float s0 = 0.f, s1 = 0.f;
        long r0 = bm + mw * 32 + f * 16 + g;
        long r1 = r0 + 8;
        #pragma unroll
        for (int nt = 0; nt < 8; nt++) {
            int col = bn + nw * 64 + nt * 8 + t2;
            if (col >= Nstore) continue;
            float2 d0 = make_float2(acc[f][nt][0], acc[f][nt][1]);
            float2 d1 = make_float2(acc[f][nt][2], acc[f][nt][3]);
            if (bias) { float b0 = bias[col], b1 = bias[col+1];
                        d0.x += b0; d0.y += b1; d1.x += b0; d1.y += b1; }
            if (res) {
                float2 q0 = *(const float2*)(res + (size_t)r0 * ldC + col);
                float2 q1 = *(const float2*)(res + (size_t)r1 * ldC + col);
                d0.x += q0.x; d0.y += q0.y; d1.x += q1.x; d1.y += q1.y;
            }
            if (relu) {
                d0.x = fmaxf(d0.x, 0.f); d0.y = fmaxf(d0.y, 0.f);
                d1.x = fmaxf(d1.x, 0.f); d1.y = fmaxf(d1.y, 0.f);
            }
            if constexpr (WRF) {
                s0 += d0.x * d0.x + d0.y * d0.y;
                s1 += d1.x * d1.x + d1.y * d1.y;
            }
            if constexpr (CHALF) {
                *(__half2*)(C16 + (size_t)r0 * ldC + col) = __floats2half2_rn(d0.x, d0.y);
                *(__half2*)(C16 + (size_t)r1 * ldC + col) = __floats2half2_rn(d1.x, d1.y);
            } else {
                *(float2*)(C + (size_t)r0 * ldC + col) = d0;
                *(float2*)(C + (size_t)r1 * ldC + col) = d1;
            }
        }
        if constexpr (WRF) {
            s0 += __shfl_xor_sync(0xffffffffu, s0, 1);
            s0 += __shfl_xor_sync(0xffffffffu, s0, 2);
            s1 += __shfl_xor_sync(0xffffffffu, s1, 1);
            s1 += __shfl_xor_sync(0xffffffffu, s1, 2);
            if ((lane & 3) == 0) {
                atomicAdd(&rsum[(int)(r0 - bm)], s0);
                atomicAdd(&rsum[(int)(r1 - bm)], s1);
            }
        }
    }
    if constexpr (WRF) {
        __syncthreads();
        if (tid < 128)
            g_rf[bm + tid] = rsqrtf(rsum[tid] * (1.f / DM) + 1e-5f);
    }
}

// ---------------- embed + batchnorm-ish scale -> fp16 ----------------------
__global__ void k_embed(const int* __restrict__ tok, const float* __restrict__ emb,
                        const float* __restrict__ bnw, const float* __restrict__ bnb)
{
    int idx = blockIdx.x * 256 + threadIdx.x;
    if (idx >= BL * EMBD) return;
    int e = idx & 127;
    int t = idx >> 7;
    float s = bnw[e] * rsqrtf(1.0f + 1e-5f);
    g_xn16[idx] = __float2half_rn(emb[tok[t] * EMBD + e] * s + bnb[e]);
}

__global__ void k_repack(const float* __restrict__ cw)
{
    int idx = blockIdx.x * 256 + threadIdx.x;
    if (idx >= DM * 384) return;
    int o = idx / 384, kg = idx % 384;
    int tap = kg >> 7, e = kg & 127;
    g_wext16[idx] = __float2half_rn(cw[(o * EMBD + e) * 3 + tap]);
}

__global__ void k_cvt(const float* __restrict__ src, __half* __restrict__ dst, int n)
{
    int i = blockIdx.x * 256 + threadIdx.x;
    if (i < n) dst[i] = __float2half_rn(src[i]);
}

// in_proj weights with norm_w folded (per layer)
__global__ void k_cvtw(const float* __restrict__ w, const float* __restrict__ nw,
                       __half* __restrict__ dst)
{
    int i = blockIdx.x * 256 + threadIdx.x;
    if (i >= NL * 512 * DM) return;
    int k = i & 127;
    int layer = i / (512 * DM);
    dst[i] = __float2half_rn(w[i] * nw[layer * DM + k]);
}

// g_xr16 = fp16(g_x * rf)
__global__ void k_normcopy()
{
    long idx4 = (long)blockIdx.x * 256 + threadIdx.x;   // BL*128/4 float4s
    float4 v = ((const float4*)g_x)[idx4];
    float rf = g_rf[idx4 >> 5];
    __half2* o = (__half2*)g_xr16 + idx4 * 2;
    o[0] = __floats2half2_rn(v.x * rf, v.y * rf);
    o[1] = __floats2half2_rn(v.z * rf, v.w * rf);
}

// ---------------- generic fp32 GEMM (small head layers) --------------------
__global__ void k_gemm(const float* __restrict__ A, const float* __restrict__ W,
                       const float* __restrict__ bias, const float* __restrict__ res,
                       float* __restrict__ C, int N, int K, int act)
{
    __shared__ float As[16][64];
    __shared__ float Ws[16][64];
    int tid = threadIdx.x;
    int tx = tid & 15, ty = tid >> 4;
    long bm = (long)blockIdx.x * 64;
    int bn = blockIdx.y * 64;
    int lrow = tid >> 2, lcol = (tid & 3) * 4;
    const float* Ap = A + (bm + lrow) * (size_t)K + lcol;
    int nrow = bn + lrow;
    const float* Wp = (nrow < N) ? (W + (size_t)nrow * K + lcol) : (const float*)0;
    float acc[4][4] = {};
    for (int kc = 0; kc < K; kc += 16) {
        float4 av = *(const float4*)(Ap + kc);
        float4 wv = make_float4(0.f, 0.f, 0.f, 0.f);
        if (Wp) wv = *(const float4*)(Wp + kc);
        As[lcol+0][lrow]=av.x; As[lcol+1][lrow]=av.y; As[lcol+2][lrow]=av.z; As[lcol+3][lrow]=av.w;
        Ws[lcol+0][lrow]=wv.x; Ws[lcol+1][lrow]=wv.y; Ws[lcol+2][lrow]=wv.z; Ws[lcol+3][lrow]=wv.w;
        __syncthreads();
        #pragma unroll
        for (int kk = 0; kk < 16; kk++) {
            float4 a4 = *(const float4*)&As[kk][ty*4];
            float4 w4 = *(const float4*)&Ws[kk][tx*4];
            acc[0][0]+=a4.x*w4.x; acc[0][1]+=a4.x*w4.y; acc[0][2]+=a4.x*w4.z; acc[0][3]+=a4.x*w4.w;
            acc[1][0]+=a4.y*w4.x; acc[1][1]+=a4.y*w4.y; acc[1][2]+=a4.y*w4.z; acc[1][3]+=a4.y*w4.w;
            acc[2][0]+=a4.z*w4.x; acc[2][1]+=a4.z*w4.y; acc[2][2]+=a4.z*w4.z; acc[2][3]+=a4.z*w4.w;
            acc[3][0]+=a4.w*w4.x; acc[3][1]+=a4.w*w4.y; acc[3][2]+=a4.w*w4.z; acc[3][3]+=a4.w*w4.w;
        }
        __syncthreads();
    }
    #pragma unroll
    for (int i = 0; i < 4; i++) {
        long row = bm + ty * 4 + i;
        #pragma unroll
        for (int j = 0; j < 4; j++) {
            int col = bn + tx * 4 + j;
            if (col < N) {
                float v = acc[i][j];
                if (bias) v += bias[col];
                if (res)  v += res[row * (size_t)N + col];
                if (act)  v = fmaxf(v, 0.f);
                C[row * (size_t)N + col] = v;
            }
        }
    }
}

// ---------------- depthwise causal conv (k=4) + silu, fp16 in/out ----------
__global__ void k_dwconv(const float* __restrict__ w, const float* __restrict__ bias)
{
    int b  = blockIdx.y;
    int l0 = blockIdx.x * 16;
    int d  = threadIdx.x;
    float w0 = w[d*4+0], w1 = w[d*4+1], w2 = w[d*4+2], w3 = w[d*4+3];
    float bb = bias[d];
    const __half* xp = g_xz16 + (size_t)b * Lsz * 512 + d;
    float v[19];
    #pragma unroll
    for (int j = 0; j < 19; j++) {
        int ls = l0 + j - 3;
        v[j] = (ls >= 0) ? __half2float(xp[(size_t)ls * 512]) : 0.f;
    }
    __half* op = g_xc16 + ((size_t)b * Lsz + l0) * DI + d;
    #pragma unroll
    for (int t = 0; t < 16; t++) {
        float a = v[t]*w0 + v[t+1]*w1 + v[t+2]*w2 + v[t+3]*w3 + bb;
        op[(size_t)t * DI] = __float2half_rn(a / (1.f + __expf(-a)));
    }
}

// ================= chunked selective scan (3-pass) ==========================
// packed-f32x2 dt: aa = bd + row[0:8] . dtw  (4 packed FMA + horizontal add)
__device__ __forceinline__ void dt_pk(const float* __restrict__ row,
                                      ull ww01, ull ww23, ull ww45, ull ww67,
                                      float bd, float& dt, float& p)
{
    const ulonglong2* r2 = (const ulonglong2*)row;
    ulonglong2 ra = r2[0], rb = r2[1];
    ull acc2 = mul2_(ra.x, ww01);
    acc2 = fma2_(ra.y, ww23, acc2);
    acc2 = fma2_(rb.x, ww45, acc2);
    acc2 = fma2_(rb.y, ww67, acc2);
    float aa0, aa1;
    up2(acc2, aa0, aa1);
    float aa = bd + aa0 + aa1;
    float e = __expf(aa);
    p  = __fdividef(1.f, 1.f + e);
    dt = (aa > 15.f) ? aa : -__logf(p);
}
__device__ __forceinline__ void dt_smem(const float* __restrict__ row,
                                        float4 w0, float4 w1, float bd,
                                        float& dt, float& p)
{
    float4 r0 = *(const float4*)(row);
    float4 r1 = *(const float4*)(row + 4);
    float aa = bd + r0.x*w0.x + r0.y*w0.y + r0.z*w0.z + r0.w*w0.w
                  + r1.x*w1.x + r1.y*w1.y + r1.z*w1.z + r1.w*w1.w;
    float e = __expf(aa);
    p  = __fdividef(1.f, 1.f + e);
    dt = (aa > 15.f) ? aa : -__logf(p);
}

__global__ void __launch_bounds__(256)
k_scanA(const float* __restrict__ Alog,
        const float* __restrict__ dtw, const float* __restrict__ dtb)
{
    __shared__ __align__(16) float sdbl[CLEN * 40];
    int c = blockIdx.x, b = blockIdx.y, d = threadIdx.x;

    const float* gsrc = g_dbl + ((size_t)b * Lsz + c * CLEN) * 40;
    for (int i = d; i < CLEN * 40 / 4; i += 256)
        ((float4*)sdbl)[i] = ((const float4*)gsrc)[i];

    float4 w0 = ((const float4*)(dtw + d * 8))[0];
    float4 w1 = ((const float4*)(dtw + d * 8))[1];
    ull ww01 = pk2(w0.x, w0.y), ww23 = pk2(w0.z, w0.w);
    ull ww45 = pk2(w1.x, w1.y), ww67 = pk2(w1.z, w1.w);
    float bd = dtb[d];

    bool fast = true;
    float a[DS];
    #pragma unroll
    for (int s = 0; s < DS; s++) {
        a[s] = -expf(Alog[d * DS + s]);
        if (fabsf(a[s] + (float)(s + 1)) > 1e-4f * (float)(s + 1)) fast = false;
    }
    float sumdt = 0.f;

    const __half* up = g_xc16 + ((size_t)b * Lsz + c * CLEN) * DI + d;
    float* slot = g_hc + (((size_t)b * NCH + c) * DI + d) * DS;
    __syncthreads();

    if (fast) {
        ull h2[8];
        #pragma unroll
        for (int q = 0; q < 8; q++) h2[q] = 0ull;
        for (int l = 0; l < CLEN; l++) {
            const float* row = sdbl + l * 40;
            float dt, p;
            dt_pk(row, ww01, ww23, ww45, ww67, bd, dt, p);
            float w = dt * __half2float(up[(size_t)l * DI]);
            sumdt += dt;
            ull ww = pk2(w, w);
            float p2 = p * p;
            ull d01 = pk2(p, p2);
            ull d23 = pk2(p2 * p, p2 * p2);
            ull q44 = pk2(p2 * p2, p2 * p2);
            const ulonglong2* B2 = (const ulonglong2*)(row + 8);
            #pragma unroll
            for (int g = 0; g < 4; g++) {
                ulonglong2 Bv = B2[g];
                ull wb01 = mul2_(Bv.x, ww);
                ull wb23 = mul2_(Bv.y, ww);
                h2[2*g+0] = fma2_(h2[2*g+0], d01, wb01);
                h2[2*g+1] = fma2_(h2[2*g+1], d23, wb23);
                if (g < 3) { d01 = mul2_(d01, q44); d23 = mul2_(d23, q44); }
            }
        }
        #pragma unroll
        for (int q = 0; q < 4; q++)
            ((ulonglong2*)slot)[q] = make_ulonglong2(h2[2*q], h2[2*q+1]);
    } else {
        float h[DS];
        #pragma unroll
        for (int s = 0; s < DS; s++) h[s] = 0.f;
        for (int l = 0; l < CLEN; l++) {
            const float* row = sdbl + l * 40;
            float dt, p;
            dt_smem(row, w0, w1, bd, dt, p);
            float w = dt * __half2float(up[(size_t)l * DI]);
            sumdt += dt;
            #pragma unroll
            for (int s = 0; s < DS; s++) {
                float dA = __expf(dt * a[s]);
                h[s] = dA * h[s] + w * row[8 + s];
            }
        }
        #pragma unroll
        for (int q = 0; q < 4; q++)
            ((float4*)slot)[q] = make_float4(h[4*q], h[4*q+1], h[4*q+2], h[4*q+3]);
    }
    g_sd[((size_t)b * NCH + c) * DI + d] = sumdt;
}

__global__ void __launch_bounds__(256)
k_scanB(const float* __restrict__ Alog)
{
    int b = blockIdx.x, d = threadIdx.x;
    float a[DS];
    #pragma unroll
    for (int s = 0; s < DS; s++) a[s] = -expf(Alog[d * DS + s]);
    float hp[DS];
    #pragma unroll
    for (int s = 0; s < DS; s++) hp[s] = 0.f;

    for (int c = 0; c < NCH; c++) {
        float* slot = g_hc + (((size_t)b * NCH + c) * DI + d) * DS;
        float sd = g_sd[((size_t)b * NCH + c) * DI + d];
        float hl[DS];
        #pragma unroll
        for (int q = 0; q < 4; q++) {
            float4 v = ((const float4*)slot)[q];
            hl[4*q] = v.x; hl[4*q+1] = v.y; hl[4*q+2] = v.z; hl[4*q+3] = v.w;
        }
        #pragma unroll
        for (int q = 0; q < 4; q++)
            ((float4*)slot)[q] = make_float4(hp[4*q], hp[4*q+1], hp[4*q+2], hp[4*q+3]);
        #pragma unroll
        for (int s = 0; s < DS; s++)
            hp[s] = __expf(a[s] * sd) * hp[s] + hl[s];
    }
}

__global__ void __launch_bounds__(256)
k_scanC(const float* __restrict__ Alog,
        const float* __restrict__ dtw, const float* __restrict__ dtb,
        const float* __restrict__ Dp)
{
    __shared__ __align__(16) float sdbl[CLEN * 40];
    int c = blockIdx.x, b = blockIdx.y, d = threadIdx.x;

    const float* gsrc = g_dbl + ((size_t)b * Lsz + c * CLEN) * 40;
    for (int i = d; i < CLEN * 40 / 4; i += 256)
        ((float4*)sdbl)[i] = ((const float4*)gsrc)[i];

    float4 w0 = ((const float4*)(dtw + d * 8))[0];
    float4 w1 = ((const float4*)(dtw + d * 8))[1];
    ull ww01 = pk2(w0.x, w0.y), ww23 = pk2(w0.z, w0.w);
    ull ww45 = pk2(w1.x, w1.y), ww67 = pk2(w1.z, w1.w);
    float bd = dtb[d];
    float Dv = Dp[d];

    bool fast = true;
    float a[DS];
    #pragma unroll
    for (int s = 0; s < DS; s++) {
        a[s] = -expf(Alog[d * DS + s]);
        if (fabsf(a[s] + (float)(s + 1)) > 1e-4f * (float)(s + 1)) fast = false;
    }
    const float* slot = g_hc + (((size_t)b * NCH + c) * DI + d) * DS;

    const __half* up = g_xc16 + ((size_t)b * Lsz + c * CLEN) * DI + d;
    const __half* zp = g_xz16 + ((size_t)b * Lsz + c * CLEN) * 512 + 256 + d;
    __half*       yp = g_y16  + ((size_t)b * Lsz + c * CLEN) * DI + d;
    __syncthreads();

    if (fast) {
        ull h2[8];
        #pragma unroll
        for (int q = 0; q < 4; q++) {
            ulonglong2 v = ((const ulonglong2*)slot)[q];
            h2[2*q] = v.x; h2[2*q+1] = v.y;
        }
        for (int l = 0; l < CLEN; l++) {
            const float* row = sdbl + l * 40;
            float dt, p;
            dt_pk(row, ww01, ww23, ww45, ww67, bd, dt, p);
            float u = __half2float(up[(size_t)l * DI]);
            float z = __half2float(zp[(size_t)l * 512]);
            float w = dt * u;
            ull ww = pk2(w, w);
            float p2 = p * p;
            ull d01 = pk2(p, p2);
            ull d23 = pk2(p2 * p, p2 * p2);
            ull q44 = pk2(p2 * p2, p2 * p2);
            const ulonglong2* B2 = (const ulonglong2*)(row + 8);
            const ulonglong2* C2 = (const ulonglong2*)(row + 24);
            ull yac = 0ull;   // (0.f, 0.f)
            #pragma unroll
            for (int g = 0; g < 4; g++) {
                ulonglong2 Bv = B2[g], Cv = C2[g];
                ull wb01 = mul2_(Bv.x, ww);
                ull wb23 = mul2_(Bv.y, ww);
                h2[2*g+0] = fma2_(h2[2*g+0], d01, wb01);
                h2[2*g+1] = fma2_(h2[2*g+1], d23, wb23);
                yac = fma2_(h2[2*g+0], Cv.x, yac);
                yac = fma2_(h2[2*g+1], Cv.y, yac);
                if (g < 3) { d01 = mul2_(d01, q44); d23 = mul2_(d23, q44); }
            }
            float ya, yb;
            up2(yac, ya, yb);
            float y = ya + yb;
            float sz = __fdividef(z, 1.f + __expf(-z));
            yp[(size_t)l * DI] = __float2half_rn((y + u * Dv) * sz);
        }
    } else {
        float h[DS];
        #pragma unroll
        for (int q = 0; q < 4; q++) {
            float4 v = ((const float4*)slot)[q];
            h[4*q] = v.x; h[4*q+1] = v.y; h[4*q+2] = v.z; h[4*q+3] = v.w;
        }
        for (int l = 0; l < CLEN; l++) {
            const float* row = sdbl + l * 40;
            float dt, p;
            dt_smem(row, w0, w1, bd, dt, p);
            float u = __half2float(up[(size_t)l * DI]);
            float z = __half2float(zp[(size_t)l * 512]);
            float w = dt * u;
            float yacc = 0.f;
            #pragma unroll
            for (int s = 0; s < DS; s++) {
                float dA = __expf(dt * a[s]);
                h[s] = dA * h[s] + w * row[8 + s];
                yacc += h[s] * row[24 + s];
            }
            float sz = __fdividef(z, 1.f + __expf(-z));
            yp[(size_t)l * DI] = __float2half_rn((yacc + u * Dv) * sz);
        }
    }
}

// ---------------- masked mean pool: 2-stage ---------------------------------
__global__ void k_pool1(const float* __restrict__ mask)
{
    int b = blockIdx.x, s = blockIdx.y;
    int e = threadIdx.x;
    const float* xp = g_x + ((size_t)b * Lsz + s * 128) * DM + e;
    const float* mp = mask + (size_t)b * Lsz + s * 128;
    float acc = 0.f, ms = 0.f;
    for (int l = 0; l < 128; l++) {
        float m = mp[l];
        acc += xp[(size_t)l * DM] * m;
        ms += m;
    }
    g_poolp[(b * 16 + s) * DM + e] = acc;
    if (e == 0) g_msum[b * 16 + s] = ms;
}
__global__ void k_pool2()
{
    int b = blockIdx.x, e = threadIdx.x;
    float acc = 0.f, ms = 0.f;
    for (int s = 0; s < 16; s++) {
        acc += g_poolp[(b * 16 + s) * DM + e];
        ms += g_msum[b * 16 + s];
    }
    g_pool[b * DM + e] = acc / fmaxf(ms, 1e-9f);
}

__global__ void k_mlp3(const float* __restrict__ w, const float* __restrict__ bias,
                       float* __restrict__ out)
{
    int t = threadIdx.x;
    if (t >= Bsz * 3) return;
    int bb = t / 3, n = t - bb * 3;
    const float* hp = g_h2 + bb * 512;
    const float* wp = w + n * 512;
    float acc = bias[n];
    for (int k = 0; k < 512; k++) acc += hp[k] * wp[k];
    out[bb * 3 + n] = acc;
}

// ---------------- launch ----------------------------------------------------
extern "C" void kernel_launch(void* const* d_in, const int* in_sizes, int n_in,
                              void* d_out, int out_size)
{
    const int*   tokens = (const int*)  d_in[0];
    const float* mask   = (const float*)d_in[1];
    const float* emb    = (const float*)d_in[2];
    const float* bn_w   = (const float*)d_in[3];
    const float* bn_b   = (const float*)d_in[4];
    const float* conv_w = (const float*)d_in[5];
    const float* conv_b = (const float*)d_in[6];
    const float* in_w   = (const float*)d_in[7];
    const float* c1_w   = (const float*)d_in[8];
    const float* c1_b   = (const float*)d_in[9];
    const float* xp_w   = (const float*)d_in[10];
    const float* dtp_w  = (const float*)d_in[11];
    const float* dtp_b  = (const float*)d_in[12];
    const float* A_log  = (const float*)d_in[13];
    const float* D_p    = (const float*)d_in[14];
    const float* out_w  = (const float*)d_in[15];
    const float* norm_w = (const float*)d_in[16];
    const float* l1w    = (const float*)d_in[17];
    const float* l1b    = (const float*)d_in[18];
    const float* l2w    = (const float*)d_in[19];
    const float* l2b    = (const float*)d_in[20];
    const float* l3w    = (const float*)d_in[21];
    const float* l3b    = (const float*)d_in[22];
    float* out = (float*)d_out;

    float *p_x, *p_dbl, *p_pool, *p_h1, *p_h2;
    __half *p_xn16, *p_xr16, *p_xz16, *p_xc16, *p_y16, *p_wext16, *p_inw16, *p_xpw16, *p_outw16;
    cudaGetSymbolAddress((void**)&p_xn16,  g_xn16);
    cudaGetSymbolAddress((void**)&p_x,     g_x);
    cudaGetSymbolAddress((void**)&p_xr16,  g_xr16);
    cudaGetSymbolAddress((void**)&p_xz16,  g_xz16);
    cudaGetSymbolAddress((void**)&p_xc16,  g_xc16);
    cudaGetSymbolAddress((void**)&p_dbl,   g_dbl);
    cudaGetSymbolAddress((void**)&p_y16,   g_y16);
    cudaGetSymbolAddress((void**)&p_pool,  g_pool);
    cudaGetSymbolAddress((void**)&p_h1,    g_h1);
    cudaGetSymbolAddress((void**)&p_h2,    g_h2);
    cudaGetSymbolAddress((void**)&p_wext16,g_wext16);
    cudaGetSymbolAddress((void**)&p_inw16, g_inw16);
    cudaGetSymbolAddress((void**)&p_xpw16, g_xpw16);
    cudaGetSymbolAddress((void**)&p_outw16,g_outw16);

    const int SMB = 98304;  // 3 x (A 16K | B 16K)
    cudaFuncSetAttribute(k_hmm<0,false,false>, cudaFuncAttributeMaxDynamicSharedMemorySize, SMB);
    cudaFuncSetAttribute(k_hmm<0,false,true>,  cudaFuncAttributeMaxDynamicSharedMemorySize, SMB);
    cudaFuncSetAttribute(k_hmm<0,true,false>,  cudaFuncAttributeMaxDynamicSharedMemorySize, SMB);
    cudaFuncSetAttribute(k_hmm<2,false,true>,  cudaFuncAttributeMaxDynamicSharedMemorySize, SMB);

    // weight conversions (tiny)
    k_cvtw<<<(NL*512*DM + 255)/256, 256>>>(in_w, norm_w, p_inw16);
    k_cvt<<<(NL*40*DI  + 255)/256, 256>>>(xp_w,  p_xpw16,  NL*40*DI);
    k_cvt<<<(NL*DM*DI  + 255)/256, 256>>>(out_w, p_outw16, NL*DM*DI);
    k_repack<<<(DM * 384 + 255) / 256, 256>>>(conv_w);
    k_embed<<<BL * EMBD / 256, 256>>>(tokens, emb, bn_w, bn_b);

    // front conv: implicit GEMM, bias+relu -> g_x; also computes g_rf
    k_hmm<2,false,true><<<dim3(BL / 128, 1), 256, SMB>>>(
        p_xn16, p_wext16, conv_b, (const float*)0,
        p_x, (__half*)0, 384, 128, 128, 128, 1);

    for (int i = 0; i < NL; i++) {
        const float* Al = A_log + (size_t)i * DI * DS;
        const float* dw = dtp_w + (size_t)i * DI * DR;
        const float* db = dtp_b + (size_t)i * DI;

        // normalized fp16 copy of residual (rf from previous GEMM)
        k_normcopy<<<BL / 8, 256>>>();
        // in_proj (norm_w folded into weights) -> g_xz16
        k_hmm<0,true,false><<<dim3(BL / 128, 4), 256, SMB>>>(
            p_xr16, p_inw16 + (size_t)i * 512 * DM, (const float*)0, (const float*)0,
            (float*)0, p_xz16, 128, 512, 512, 512, 0);
        k_dwconv<<<dim3(Lsz / 16, Bsz), 256>>>(c1_w + (size_t)i * DI * 4, c1_b + (size_t)i * DI);
        // x_proj -> g_dbl
        k_hmm<0,false,false><<<dim3(BL / 128, 1), 256, SMB>>>(
            p_xc16, p_xpw16 + (size_t)i * 40 * DI, (const float*)0, (const float*)0,
            p_dbl, (__half*)0, 256, 40, 40, 40, 0);
        k_scanA<<<dim3(NCH, Bsz), 256>>>(Al, dw, db);
        k_scanB<<<Bsz, 256>>>(Al);
        k_scanC<<<dim3(NCH, Bsz), 256>>>(Al, dw, db, D_p + (size_t)i * DI);
        // out_proj: += residual -> g_x; also computes g_rf
        k_hmm<0,false,true><<<dim3(BL / 128, 1), 256, SMB>>>(
            p_y16, p_outw16 + (size_t)i * DM * DI, (const float*)0, p_x,
            p_x, (__half*)0, 256, 128, 128, 128, 0);
    }

    k_pool1<<<dim3(Bsz, 16), 128>>>(mask);
    k_pool2<<<Bsz, 128>>>();
    k_gemm<<<dim3(1, 512 / 64), 256>>>(p_pool, l1w, l1b, (const float*)0, p_h1, 512, DM, 1);
    k_gemm<<<dim3(1, 512 / 64), 256>>>(p_h1,   l2w, l2b, (const float*)0, p_h2, 512, 512, 1);
    k_mlp3<<<1, 256>>>(l3w, l3b, out);
}